// round 6
// baseline (speedup 1.0000x reference)
#include <cuda_runtime.h>
#include <stdint.h>
#include <math.h>

// dims: b=4, n=4096, d=128, hid=512, CHUNK=64
#define NTOK 16384
#define D 128
#define HID 512
#define NC 64
#define BATCH 4
#define SLICES 8
#define NTHR 512
// stage: A packed 4096 words + B region 4608 words
#define A_WORDS 4096
#define STG 8704
#define SMEM_DYN (2*STG*4)   // 69632 bytes

// ---------------- scratch ----------------
__device__ float g_K [NTOK*D];     // full (epilogue use in g3)
__device__ float g_KR[NTOK*D];     // tf32-rounded (GEMM operand)
__device__ float g_V [NTOK*D];
__device__ float g_Q [NTOK*D];     // full (g7 residual)
__device__ float g_QR[NTOK*D];     // rounded (g6 operand)
__device__ float g_A [NTOK*HID];   // rounded at write (GEMM-only)
__device__ float g_GP[NTOK*HID];   // full (epilogue-only)
__device__ float g_dH[NTOK*D];     // rounded
__device__ float g_dZ[NTOK*HID];   // rounded
__device__ float g_A2[NTOK*HID];   // rounded
__device__ float g_seqR[NTOK*D];
__device__ float g_wkR[D*D], g_wvR[D*D], g_wqR[D*D];
__device__ float g_w1R[D*HID];
__device__ float g_w2R[HID*D];
__device__ float g_lrv [BATCH*NC];
__device__ float g_keep[BATCH*NC];
__device__ float g_eta [BATCH*NC];
__device__ float g_coef[BATCH*NC];
__device__ float g_gfp[128*D];
__device__ float g_gf [BATCH*D];
__device__ float g_w1p[BATCH*SLICES*D*HID];
__device__ float g_w2p[BATCH*SLICES*HID*D];
__device__ float g_w1f[BATCH*D*HID];   // rounded
__device__ float g_w2f[BATCH*HID*D];   // rounded

// ---------------- helpers ----------------
__device__ __forceinline__ float sigm(float x){ return 1.f/(1.f+expf(-x)); }
__device__ __forceinline__ float tanh_fast(float u){
    float e = __expf(2.f*u);
    return 1.f - __fdividef(2.f, e + 1.f);
}
__device__ __forceinline__ void gelu_both(float x, float& a, float& gp){
    const float c0 = 0.7978845608028654f, c1 = 0.044715f;
    float x2 = x*x;
    float t = tanh_fast(c0*x*(1.f + c1*x2));
    a  = 0.5f*x*(1.f + t);
    gp = 0.5f*(1.f + t) + 0.5f*x*(1.f - t*t)*c0*(1.f + 3.f*c1*x2);
}
__device__ __forceinline__ float gelu_f(float x){
    float t = tanh_fast(0.7978845608028654f*x*(1.f + 0.044715f*x*x));
    return 0.5f*x*(1.f + t);
}
__device__ __forceinline__ uint32_t cvt_tf32(float x){
    uint32_t r; asm("cvt.rna.tf32.f32 %0, %1;" : "=r"(r) : "f"(x)); return r;
}
__device__ __forceinline__ float rtf(float x){ return __uint_as_float(cvt_tf32(x)); }

__device__ __forceinline__ void mma8(float& c0, float& c1, float& c2, float& c3,
                                     uint32_t a0, uint32_t a1, uint32_t a2, uint32_t a3,
                                     uint32_t b0, uint32_t b1){
    asm volatile("mma.sync.aligned.m16n8k8.row.col.f32.tf32.tf32.f32 "
                 "{%0,%1,%2,%3}, {%4,%5,%6,%7}, {%8,%9}, {%0,%1,%2,%3};"
                 : "+f"(c0), "+f"(c1), "+f"(c2), "+f"(c3)
                 : "r"(a0), "r"(a1), "r"(a2), "r"(a3), "r"(b0), "r"(b1));
}
__device__ __forceinline__ uint32_t smem_u32(const void* p){
    uint32_t a;
    asm("{ .reg .u64 t; cvta.to.shared.u64 t, %1; cvt.u32.u64 %0, t; }" : "=r"(a) : "l"(p));
    return a;
}
__device__ __forceinline__ void cp16(uint32_t dst, const void* src){
    asm volatile("cp.async.cg.shared.global [%0], [%1], 16;" :: "r"(dst), "l"(src));
}
#define CP_COMMIT() asm volatile("cp.async.commit_group;" ::: "memory")
#define CP_WAIT0()  asm volatile("cp.async.wait_group 0;" ::: "memory")

// ---------------- A-fragment packed layout ----------------
// word = mt*512 + kb*128 + [ (lane*4+slot) ^ ((kb^(mt&3))<<2) ^ (((lane>>4)&1)<<4) ]
__device__ __forceinline__ int a_word(int mt, int kb, int lane, int slot){
    int off = lane*4 + slot;
    off ^= ((kb ^ (mt & 3)) << 2);
    off ^= (((lane >> 4) & 1) << 4);
    return mt*512 + kb*128 + off;
}

// ------------- pipelined warp-mma GEMM core: 128x128 tile, BK=32, 512 thr -------
// 16 warps = 4(m) x 4(n); warp tile 32x32 = 2 mtiles x 4 ntiles of m16n8k8.
// A packed fragments (LDS.128); B: BL=0 smem [k][n] stride 136, BL=1 [n][k] stride 36.

template<int AL>
__device__ __forceinline__ void ldgA(const float* __restrict__ Ag, int lda, int k0,
                                     int tid, float4 pa[2]) {
    #pragma unroll
    for (int j = 0; j < 2; j++) {
        int idx4 = tid + j*NTHR;
        if (AL == 0) { int r = idx4 >> 3, c = idx4 & 7;
            pa[j] = *reinterpret_cast<const float4*>(Ag + (size_t)r*lda + k0 + c*4); }
        else         { int r = idx4 >> 5, c = idx4 & 31;
            pa[j] = *reinterpret_cast<const float4*>(Ag + (size_t)(k0+r)*lda + c*4); }
    }
}

template<int AL>
__device__ __forceinline__ void stsA(uint32_t* As, int tid, const float4 pa[2]) {
    #pragma unroll
    for (int j = 0; j < 2; j++) {
        float v[4] = {pa[j].x, pa[j].y, pa[j].z, pa[j].w};
        int idx4 = tid + j*NTHR;
        if (AL == 0) {
            int r = idx4 >> 3, c = idx4 & 7;
            int mt = r >> 4, gr = r & 7, hi = (r >> 3) & 1;
            int kb = c >> 1, khi = c & 1;
            int slot = hi + 2*khi;
            #pragma unroll
            for (int i = 0; i < 4; i++)
                As[a_word(mt, kb, gr*4 + i, slot)] = __float_as_uint(v[i]);
        } else {
            int r = idx4 >> 5, c = idx4 & 31;         // r = k, cols m = 4c..4c+3
            int kb = r >> 3, tg = r & 3, khi = (r >> 2) & 1;
            int mt = c >> 2, hi = (c >> 1) & 1;
            int slot = hi + 2*khi;
            #pragma unroll
            for (int i = 0; i < 4; i++) {
                int gr = 4*(c & 1) + i;
                As[a_word(mt, kb, gr*4 + tg, slot)] = __float_as_uint(v[i]);
            }
        }
    }
}

template<int BL>
__device__ __forceinline__ void cpB(uint32_t dstb, const float* __restrict__ Bg, int ldb,
                                    int k0, int tid) {
    #pragma unroll
    for (int j = 0; j < 2; j++) {
        int idx4 = tid + j*NTHR;
        if (BL == 0) { int r = idx4 >> 5, c = idx4 & 31;
            cp16(dstb + (uint32_t)(r*136 + c*4)*4u, Bg + (size_t)(k0+r)*ldb + c*4); }
        else         { int r = idx4 >> 3, c = idx4 & 7;
            cp16(dstb + (uint32_t)(r*36 + c*4)*4u, Bg + (size_t)r*ldb + k0 + c*4); }
    }
}

__device__ __forceinline__ void ldfA(const uint32_t* As, int kb, int wm, int lane,
                                     uint32_t af[2][4]) {
    #pragma unroll
    for (int mt = 0; mt < 2; mt++) {
        int w = a_word(wm*2 + mt, kb, lane, 0);
        uint4 v = *reinterpret_cast<const uint4*>(As + w);
        af[mt][0] = v.x; af[mt][1] = v.y; af[mt][2] = v.z; af[mt][3] = v.w;
    }
}

template<int BL>
__device__ __forceinline__ void ldfB(const uint32_t* Bs, int k, int wn, int group, int tg,
                                     uint32_t bf[4][2]) {
    #pragma unroll
    for (int nt = 0; nt < 4; nt++) {
        int cb = wn*32 + nt*8 + group;
        if (BL == 0) { bf[nt][0] = Bs[(k+tg)*136 + cb]; bf[nt][1] = Bs[(k+tg+4)*136 + cb]; }
        else         { bf[nt][0] = Bs[cb*36 + k + tg];  bf[nt][1] = Bs[cb*36 + k + tg + 4]; }
    }
}

__device__ __forceinline__ void mma_step(float acc[2][4][4],
                                         const uint32_t af[2][4], const uint32_t bf[4][2]) {
    #pragma unroll
    for (int nt = 0; nt < 4; nt++)
        #pragma unroll
        for (int mt = 0; mt < 2; mt++)
            mma8(acc[mt][nt][0], acc[mt][nt][1], acc[mt][nt][2], acc[mt][nt][3],
                 af[mt][0], af[mt][1], af[mt][2], af[mt][3], bf[nt][0], bf[nt][1]);
}

template<int AL, int BL, int NCH>
__device__ __forceinline__ void mma_core(const float* __restrict__ Ag, int lda,
                                         const float* __restrict__ Bg, int ldb,
                                         float acc[2][4][4], uint32_t* smp) {
    const int tid = threadIdx.x;
    const int lane = tid & 31, group = lane >> 2, tg = lane & 3;
    const int wid = tid >> 5, wm = wid & 3, wn = wid >> 2;
    const uint32_t sbase = smem_u32(smp);
    float4 pa[2];

    ldgA<AL>(Ag, lda, 0, tid, pa);
    stsA<AL>(smp, tid, pa);
    cpB<BL>(sbase + A_WORDS*4u, Bg, ldb, 0, tid);
    CP_COMMIT();
    CP_WAIT0();
    __syncthreads();

    uint32_t af[2][2][4], bf[2][4][2];
    #pragma unroll 1
    for (int c = 0; c < NCH; c++) {
        const uint32_t* As = smp + (c & 1)*STG;
        const uint32_t* Bs = As + A_WORDS;
        uint32_t* An = smp + ((c + 1) & 1)*STG;
        bool more = (c + 1 < NCH);
        if (more) {
            ldgA<AL>(Ag, lda, (c+1)*32, tid, pa);
            cpB<BL>(sbase + (((c+1)&1)*STG + A_WORDS)*4u, Bg, ldb, (c+1)*32, tid);
            CP_COMMIT();
        }
        ldfA(As, 0, wm, lane, af[0]); ldfB<BL>(Bs, 0,  wn, group, tg, bf[0]);
        ldfA(As, 1, wm, lane, af[1]); ldfB<BL>(Bs, 8,  wn, group, tg, bf[1]);
        mma_step(acc, af[0], bf[0]);
        ldfA(As, 2, wm, lane, af[0]); ldfB<BL>(Bs, 16, wn, group, tg, bf[0]);
        mma_step(acc, af[1], bf[1]);
        if (more) stsA<AL>(An, tid, pa);
        ldfA(As, 3, wm, lane, af[1]); ldfB<BL>(Bs, 24, wn, group, tg, bf[1]);
        mma_step(acc, af[0], bf[0]);
        mma_step(acc, af[1], bf[1]);
        if (more) CP_WAIT0();
        __syncthreads();
    }
}

// epilogue index helpers (row/col local to 128x128 tile)
#define ROW_OF(mt, h)  (wm*32 + (mt)*16 + group + 8*(h))
#define COL_OF(nt)     (wn*32 + (nt)*8 + 2*tg)

// ---------------- pre-round inputs ----------------
__global__ void k_round(const float* __restrict__ seq, const float* __restrict__ wk,
                        const float* __restrict__ wv,  const float* __restrict__ wq,
                        const float* __restrict__ w1,  const float* __restrict__ w2) {
    int i4 = blockIdx.x*256 + threadIdx.x;
    const float4* src; float4* dst; int off;
    if      (i4 < 524288) { src = (const float4*)seq; dst = (float4*)g_seqR; off = i4; }
    else if (i4 < 528384) { src = (const float4*)wk;  dst = (float4*)g_wkR;  off = i4 - 524288; }
    else if (i4 < 532480) { src = (const float4*)wv;  dst = (float4*)g_wvR;  off = i4 - 528384; }
    else if (i4 < 536576) { src = (const float4*)wq;  dst = (float4*)g_wqR;  off = i4 - 532480; }
    else if (i4 < 552960) { src = (const float4*)w1;  dst = (float4*)g_w1R;  off = i4 - 536576; }
    else                  { src = (const float4*)w2;  dst = (float4*)g_w2R;  off = i4 - 552960; }
    float4 v = src[off];
    v.x = rtf(v.x); v.y = rtf(v.y); v.z = rtf(v.z); v.w = rtf(v.w);
    dst[off] = v;
}

// ---------------- scalar kernels ----------------
__device__ __forceinline__ float bred128(float v){
    __shared__ float wr[4];
    #pragma unroll
    for (int o = 16; o > 0; o >>= 1) v += __shfl_down_sync(0xffffffffu, v, o);
    int tid = threadIdx.x;
    if ((tid & 31) == 0) wr[tid >> 5] = v;
    __syncthreads();
    float r = wr[0] + wr[1] + wr[2] + wr[3];
    __syncthreads();
    return r;
}
__global__ void k_dots(const float* __restrict__ seq,
                       const float* __restrict__ wlr,  const float* __restrict__ blr,
                       const float* __restrict__ wdec, const float* __restrict__ bdec,
                       const float* __restrict__ wmom, const float* __restrict__ bmom) {
    int b = blockIdx.x >> 6, c = blockIdx.x & 63;
    int tid = threadIdx.x;
    float x = seq[((size_t)b*4096 + c*64)*D + tid];
    float s1 = bred128(x*wlr[tid]);
    float s2 = bred128(x*wdec[tid]);
    float s3 = bred128(x*wmom[tid]);
    if (tid == 0) {
        g_lrv [b*NC + c] = sigm(s1 + blr[0]);
        g_keep[b*NC + c] = 1.f - sigm(s2 + bdec[0]);
        g_eta [b*NC + c] = sigm(s3 + bmom[0]);
    }
}
__global__ void k_coef() {
    int b = threadIdx.x;
    if (b >= BATCH) return;
    float Av = 1.f, Bv = 1.f;
    g_coef[b*NC + NC-1] = -g_lrv[b*NC + NC-1]*(2.f/128.f);
    for (int j = NC-2; j >= 0; j--) {
        Bv *= g_keep[b*NC + j+1];
        Av  = Bv + g_eta[b*NC + j+1]*Av;
        g_coef[b*NC + j] = -Av*g_lrv[b*NC + j]*(2.f/128.f);
    }
}

// ---------------- G1: K/V/Q = seq @ W ----------------
__global__ __launch_bounds__(NTHR) void g1_proj() {
    extern __shared__ uint32_t smp[];
    const float* W = (blockIdx.z == 0) ? g_wkR : (blockIdx.z == 1 ? g_wvR : g_wqR);
    int row0 = blockIdx.x * 128;
    float acc[2][4][4] = {};
    mma_core<0,0,4>(g_seqR + (size_t)row0*D, D, W, D, acc, smp);
    const int tid = threadIdx.x, lane = tid & 31, group = lane >> 2, tg = lane & 3;
    const int wid = tid >> 5, wm = wid & 3, wn = wid >> 2;
    float* Of = (blockIdx.z == 0) ? g_K : (blockIdx.z == 1 ? g_V : g_Q);
    float* Or = (blockIdx.z == 0) ? g_KR : (blockIdx.z == 2 ? g_QR : nullptr);
    #pragma unroll
    for (int mt = 0; mt < 2; mt++)
        #pragma unroll
        for (int h = 0; h < 2; h++) {
            int tok = row0 + ROW_OF(mt, h);
            #pragma unroll
            for (int nt = 0; nt < 4; nt++) {
                int cc = COL_OF(nt);
                float v0 = acc[mt][nt][2*h], v1 = acc[mt][nt][2*h+1];
                *reinterpret_cast<float2*>(Of + (size_t)tok*D + cc) = make_float2(v0, v1);
                if (Or)
                    *reinterpret_cast<float2*>(Or + (size_t)tok*D + cc) =
                        make_float2(rtf(v0), rtf(v1));
            }
        }
}

// ---------------- G2: Z = K @ w1 -> gelu, gelu' ----------------
__global__ __launch_bounds__(NTHR) void g2_zgelu() {
    extern __shared__ uint32_t smp[];
    int row0 = blockIdx.x*128, n0 = blockIdx.y*128;
    float acc[2][4][4] = {};
    mma_core<0,0,4>(g_KR + (size_t)row0*D, D, g_w1R + n0, HID, acc, smp);
    const int tid = threadIdx.x, lane = tid & 31, group = lane >> 2, tg = lane & 3;
    const int wid = tid >> 5, wm = wid & 3, wn = wid >> 2;
    #pragma unroll
    for (int mt = 0; mt < 2; mt++)
        #pragma unroll
        for (int h = 0; h < 2; h++) {
            int tok = row0 + ROW_OF(mt, h);
            size_t base = (size_t)tok*HID + n0;
            #pragma unroll
            for (int nt = 0; nt < 4; nt++) {
                int cc = COL_OF(nt);
                float a0, p0, a1, p1;
                gelu_both(acc[mt][nt][2*h],   a0, p0);
                gelu_both(acc[mt][nt][2*h+1], a1, p1);
                *reinterpret_cast<float2*>(g_A  + base + cc) = make_float2(rtf(a0), rtf(a1));
                *reinterpret_cast<float2*>(g_GP + base + cc) = make_float2(p0, p1);
            }
        }
}

// ---------------- G3: H = A @ w2; rmsnorm bwd -> dH, dgamma partial -------------
__global__ __launch_bounds__(NTHR) void g3_hback(const float* __restrict__ gamma) {
    extern __shared__ uint32_t smp[];
    __shared__ float gam[128];
    const int tid = threadIdx.x;
    if (tid < 128) gam[tid] = gamma[tid];
    int row0 = blockIdx.x * 128;
    float acc[2][4][4] = {};
    mma_core<0,0,16>(g_A + (size_t)row0*HID, HID, g_w2R, D, acc, smp);
    const int lane = tid & 31, group = lane >> 2, tg = lane & 3;
    const int wid = tid >> 5, wm = wid & 3, wn = wid >> 2;
    float* rs = reinterpret_cast<float*>(smp);        // [4][128]
    float* cs = reinterpret_cast<float*>(smp) + 512;  // [4][128]

    #pragma unroll
    for (int mt = 0; mt < 2; mt++)
        #pragma unroll
        for (int h = 0; h < 2; h++) {
            float s = 0;
            #pragma unroll
            for (int nt = 0; nt < 4; nt++)
                s += acc[mt][nt][2*h]*acc[mt][nt][2*h] + acc[mt][nt][2*h+1]*acc[mt][nt][2*h+1];
            s += __shfl_xor_sync(0xffffffffu, s, 1);
            s += __shfl_xor_sync(0xffffffffu, s, 2);
            if (tg == 0) rs[wn*128 + ROW_OF(mt, h)] = s;
        }
    __syncthreads();
    float ir[2][2], cf[2][2];
    #pragma unroll
    for (int mt = 0; mt < 2; mt++)
        #pragma unroll
        for (int h = 0; h < 2; h++) {
            int r = ROW_OF(mt, h);
            float s = rs[r] + rs[128 + r] + rs[256 + r] + rs[384 + r];
            ir[mt][h] = rsqrtf(s*(1.f/128.f) + 1e-6f);
            int tok = row0 + r;
            cf[mt][h] = g_coef[(tok >> 12)*NC + ((tok & 4095) >> 6)];
        }
    __syncthreads();

    #pragma unroll
    for (int mt = 0; mt < 2; mt++)
        #pragma unroll
        for (int h = 0; h < 2; h++) {
            int r = ROW_OF(mt, h), tok = row0 + r;
            float irr = ir[mt][h], cfv = cf[mt][h];
            float dsum = 0;
            #pragma unroll
            for (int nt = 0; nt < 4; nt++) {
                int cc = COL_OF(nt);
                float2 kk = *reinterpret_cast<const float2*>(g_K + (size_t)tok*D + cc);
                float2 vv = *reinterpret_cast<const float2*>(g_V + (size_t)tok*D + cc);
                float hn0 = acc[mt][nt][2*h]*irr,   hn1 = acc[mt][nt][2*h+1]*irr;
                float dp0 = cfv*(hn0*gam[cc] + kk.x - vv.x);
                float dp1 = cfv*(hn1*gam[cc+1] + kk.y - vv.y);
                dsum += dp0*gam[cc]*hn0 + dp1*gam[cc+1]*hn1;
            }
            dsum += __shfl_xor_sync(0xffffffffu, dsum, 1);
            dsum += __shfl_xor_sync(0xffffffffu, dsum, 2);
            if (tg == 0) rs[wn*128 + r] = dsum;
        }
    __syncthreads();

    float colp[4][2] = {};
    #pragma unroll
    for (int mt = 0; mt < 2; mt++)
        #pragma unroll
        for (int h = 0; h < 2; h++) {
            int r = ROW_OF(mt, h), tok = row0 + r;
            float irr = ir[mt][h], cfv = cf[mt][h];
            float rd = (rs[r] + rs[128 + r] + rs[256 + r] + rs[384 + r])*(1.f/128.f);
            #pragma unroll
            for (int nt = 0; nt < 4; nt++) {
                int cc = COL_OF(nt);
                float2 kk = *reinterpret_cast<const float2*>(g_K + (size_t)tok*D + cc);
                float2 vv = *reinterpret_cast<const float2*>(g_V + (size_t)tok*D + cc);
                float hn0 = acc[mt][nt][2*h]*irr,   hn1 = acc[mt][nt][2*h+1]*irr;
                float dp0 = cfv*(hn0*gam[cc] + kk.x - vv.x);
                float dp1 = cfv*(hn1*gam[cc+1] + kk.y - vv.y);
                float o0 = irr*(dp0*gam[cc]   - hn0*rd);
                float o1 = irr*(dp1*gam[cc+1] - hn1*rd);
                *reinterpret_cast<float2*>(g_dH + (size_t)tok*D + cc) =
                    make_float2(rtf(o0), rtf(o1));
                colp[nt][0] += dp0*hn0;
                colp[nt][1] += dp1*hn1;
            }
        }
    __syncthreads();
    #pragma unroll
    for (int nt = 0; nt < 4; nt++)
        #pragma unroll
        for (int j = 0; j < 2; j++) {
            float v = colp[nt][j];
            v += __shfl_xor_sync(0xffffffffu, v, 4);
            v += __shfl_xor_sync(0xffffffffu, v, 8);
            v += __shfl_xor_sync(0xffffffffu, v, 16);
            if (group == 0) cs[wm*128 + COL_OF(nt) + j] = v;
        }
    __syncthreads();
    if (tid < 128) {
        float s = cs[tid] + cs[128 + tid] + cs[256 + tid] + cs[384 + tid];
        g_gfp[blockIdx.x*128 + tid] = s;
    }
}

// ---------------- G4: dZ = (dH @ w2^T) * GP ----------------
__global__ __launch_bounds__(NTHR) void g4_da() {
    extern __shared__ uint32_t smp[];
    int row0 = blockIdx.x*128, n0 = blockIdx.y*128;
    float acc[2][4][4] = {};
    mma_core<0,1,4>(g_dH + (size_t)row0*D, D, g_w2R + (size_t)n0*D, D, acc, smp);
    const int tid = threadIdx.x, lane = tid & 31, group = lane >> 2, tg = lane & 3;
    const int wid = tid >> 5, wm = wid & 3, wn = wid >> 2;
    #pragma unroll
    for (int mt = 0; mt < 2; mt++)
        #pragma unroll
        for (int h = 0; h < 2; h++) {
            int tok = row0 + ROW_OF(mt, h);
            size_t base = (size_t)tok*HID + n0;
            #pragma unroll
            for (int nt = 0; nt < 4; nt++) {
                int cc = COL_OF(nt);
                float2 gp = *reinterpret_cast<const float2*>(g_GP + base + cc);
                *reinterpret_cast<float2*>(g_dZ + base + cc) =
                    make_float2(rtf(acc[mt][nt][2*h]*gp.x), rtf(acc[mt][nt][2*h+1]*gp.y));
            }
        }
}

// ---------------- G5 merged: y=0 w1p = K^T@dZ ; y=1 w2p = A^T@dH ----------------
__global__ __launch_bounds__(NTHR) void g5_wp() {
    extern __shared__ uint32_t smp[];
    int z = blockIdx.z, bh = z >> 3, sl = z & 7;
    int t0 = bh*4096 + sl*512;
    const float* Ag; const float* Bg; int lda, ldb;
    if (blockIdx.y == 0) {
        Ag = g_KR + (size_t)t0*D;                lda = D;
        Bg = g_dZ + (size_t)t0*HID + blockIdx.x*128; ldb = HID;
    } else {
        Ag = g_A + (size_t)t0*HID + blockIdx.x*128; lda = HID;
        Bg = g_dH + (size_t)t0*D;                ldb = D;
    }
    float acc[2][4][4] = {};
    mma_core<1,0,16>(Ag, lda, Bg, ldb, acc, smp);
    const int tid = threadIdx.x, lane = tid & 31, group = lane >> 2, tg = lane & 3;
    const int wid = tid >> 5, wm = wid & 3, wn = wid >> 2;
    if (blockIdx.y == 0) {
        float* C = g_w1p + (size_t)z*(D*HID);
        int n0 = blockIdx.x * 128;
        #pragma unroll
        for (int mt = 0; mt < 2; mt++)
            #pragma unroll
            for (int h = 0; h < 2; h++) {
                int r = ROW_OF(mt, h);
                #pragma unroll
                for (int nt = 0; nt < 4; nt++)
                    *reinterpret_cast<float2*>(C + (size_t)r*HID + n0 + COL_OF(nt)) =
                        make_float2(acc[mt][nt][2*h], acc[mt][nt][2*h+1]);
            }
    } else {
        float* C = g_w2p + (size_t)z*(HID*D);
        int m0 = blockIdx.x * 128;
        #pragma unroll
        for (int mt = 0; mt < 2; mt++)
            #pragma unroll
            for (int h = 0; h < 2; h++) {
                int r = m0 + ROW_OF(mt, h);
                #pragma unroll
                for (int nt = 0; nt < 4; nt++)
                    *reinterpret_cast<float2*>(C + (size_t)r*D + COL_OF(nt)) =
                        make_float2(acc[mt][nt][2*h], acc[mt][nt][2*h+1]);
            }
    }
}

// ---------------- reduce split-K partials + dgamma ----------------
__global__ void k_reduce() {
    int i = blockIdx.x*256 + threadIdx.x;
    if (i < BATCH*D*HID) {
        int bh = i >> 16, off = i & 65535;
        float s1 = 0, s2 = 0;
        #pragma unroll
        for (int s = 0; s < SLICES; s++) {
            s1 += g_w1p[(size_t)(bh*SLICES + s)*(D*HID) + off];
            s2 += g_w2p[(size_t)(bh*SLICES + s)*(HID*D) + off];
        }
        g_w1f[i] = rtf(s1);
        g_w2f[i] = rtf(s2);
    }
    if (i < BATCH*D) {
        int bh = i >> 7, col = i & 127;
        float s = 0;
        #pragma unroll
        for (int q = 0; q < 32; q++) s += g_gfp[(bh*32 + q)*128 + col];
        g_gf[i] = s;
    }
}

// ---------------- G6: A2 = gelu(Q @ w1f) ----------------
__global__ __launch_bounds__(NTHR) void g6_z2() {
    extern __shared__ uint32_t smp[];
    int row0 = blockIdx.x*128, n0 = blockIdx.y*128;
    int bh = row0 >> 12;
    float acc[2][4][4] = {};
    mma_core<0,0,4>(g_QR + (size_t)row0*D, D, g_w1f + (size_t)bh*(D*HID) + n0, HID, acc, smp);
    const int tid = threadIdx.x, lane = tid & 31, group = lane >> 2, tg = lane & 3;
    const int wid = tid >> 5, wm = wid & 3, wn = wid >> 2;
    #pragma unroll
    for (int mt = 0; mt < 2; mt++)
        #pragma unroll
        for (int h = 0; h < 2; h++) {
            int tok = row0 + ROW_OF(mt, h);
            size_t base = (size_t)tok*HID + n0;
            #pragma unroll
            for (int nt = 0; nt < 4; nt++) {
                int cc = COL_OF(nt);
                *reinterpret_cast<float2*>(g_A2 + base + cc) =
                    make_float2(rtf(gelu_f(acc[mt][nt][2*h])),
                                rtf(gelu_f(acc[mt][nt][2*h+1])));
            }
        }
}

// ---------------- G7: out = rmsnorm(A2 @ w2f)*gf + Q ----------------
__global__ __launch_bounds__(NTHR) void g7_out(float* __restrict__ out) {
    extern __shared__ uint32_t smp[];
    __shared__ float gfs[128];
    const int tid = threadIdx.x;
    int row0 = blockIdx.x * 128;
    int bh = row0 >> 12;
    if (tid < 128) gfs[tid] = g_gf[bh*D + tid];
    float acc[2][4][4] = {};
    mma_core<0,0,16>(g_A2 + (size_t)row0*HID, HID, g_w2f + (size_t)bh*(HID*D), D, acc, smp);
    const int lane = tid & 31, group = lane >> 2, tg = lane & 3;
    const int wid = tid >> 5, wm = wid & 3, wn = wid >> 2;
    float* rs = reinterpret_cast<float*>(smp);  // [4][128]
    #pragma unroll
    for (int mt = 0; mt < 2; mt++)
        #pragma unroll
        for (int h = 0; h < 2; h++) {
            float s = 0;
            #pragma unroll
            for (int nt = 0; nt < 4; nt++)
                s += acc[mt][nt][2*h]*acc[mt][nt][2*h] + acc[mt][nt][2*h+1]*acc[mt][nt][2*h+1];
            s += __shfl_xor_sync(0xffffffffu, s, 1);
            s += __shfl_xor_sync(0xffffffffu, s, 2);
            if (tg == 0) rs[wn*128 + ROW_OF(mt, h)] = s;
        }
    __syncthreads();
    #pragma unroll
    for (int mt = 0; mt < 2; mt++)
        #pragma unroll
        for (int h = 0; h < 2; h++) {
            int r = ROW_OF(mt, h), tok = row0 + r;
            float s = rs[r] + rs[128 + r] + rs[256 + r] + rs[384 + r];
            float irr = rsqrtf(s*(1.f/128.f) + 1e-6f);
            #pragma unroll
            for (int nt = 0; nt < 4; nt++) {
                int cc = COL_OF(nt);
                float2 qq = *reinterpret_cast<const float2*>(g_Q + (size_t)tok*D + cc);
                *reinterpret_cast<float2*>(out + (size_t)tok*D + cc) =
                    make_float2(acc[mt][nt][2*h]*irr*gfs[cc] + qq.x,
                                acc[mt][nt][2*h+1]*irr*gfs[cc+1] + qq.y);
            }
        }
}

// ---------------- launch ----------------
extern "C" void kernel_launch(void* const* d_in, const int* in_sizes, int n_in,
                              void* d_out, int out_size) {
    (void)in_sizes; (void)n_in; (void)out_size;
    const float* seq  = (const float*)d_in[0];
    const float* wk   = (const float*)d_in[1];
    const float* wv   = (const float*)d_in[2];
    const float* wq   = (const float*)d_in[3];
    const float* wlr  = (const float*)d_in[4];
    const float* blr  = (const float*)d_in[5];
    const float* wdec = (const float*)d_in[6];
    const float* bdec = (const float*)d_in[7];
    const float* wmom = (const float*)d_in[8];
    const float* bmom = (const float*)d_in[9];
    const float* gamma= (const float*)d_in[10];
    const float* w1   = (const float*)d_in[11];
    const float* w2   = (const float*)d_in[12];
    float* out = (float*)d_out;

    cudaFuncSetAttribute(g1_proj,  cudaFuncAttributeMaxDynamicSharedMemorySize, SMEM_DYN);
    cudaFuncSetAttribute(g2_zgelu, cudaFuncAttributeMaxDynamicSharedMemorySize, SMEM_DYN);
    cudaFuncSetAttribute(g3_hback, cudaFuncAttributeMaxDynamicSharedMemorySize, SMEM_DYN);
    cudaFuncSetAttribute(g4_da,    cudaFuncAttributeMaxDynamicSharedMemorySize, SMEM_DYN);
    cudaFuncSetAttribute(g5_wp,    cudaFuncAttributeMaxDynamicSharedMemorySize, SMEM_DYN);
    cudaFuncSetAttribute(g6_z2,    cudaFuncAttributeMaxDynamicSharedMemorySize, SMEM_DYN);
    cudaFuncSetAttribute(g7_out,   cudaFuncAttributeMaxDynamicSharedMemorySize, SMEM_DYN);

    k_round <<<2224, 256>>>(seq, wk, wv, wq, w1, w2);
    k_dots  <<<BATCH*NC, 128>>>(seq, wlr, blr, wdec, bdec, wmom, bmom);
    k_coef  <<<1, 32>>>();
    g1_proj <<<dim3(NTOK/128, 1, 3), NTHR, SMEM_DYN>>>();
    g2_zgelu<<<dim3(NTOK/128, HID/128), NTHR, SMEM_DYN>>>();
    g3_hback<<<NTOK/128, NTHR, SMEM_DYN>>>(gamma);
    g4_da   <<<dim3(NTOK/128, HID/128), NTHR, SMEM_DYN>>>();
    g5_wp   <<<dim3(HID/128, 2, BATCH*SLICES), NTHR, SMEM_DYN>>>();
    k_reduce<<<(BATCH*D*HID)/256, 256>>>();
    g6_z2   <<<dim3(NTOK/128, HID/128), NTHR, SMEM_DYN>>>();
    g7_out  <<<NTOK/128, NTHR, SMEM_DYN>>>(out);
}

// round 7
// speedup vs baseline: 1.3505x; 1.3505x over previous
#include <cuda_runtime.h>
#include <cuda_fp16.h>
#include <stdint.h>
#include <math.h>

// dims: b=4, n=4096, d=128, hid=512, CHUNK=64
#define NTOK 16384
#define D 128
#define HID 512
#define NC 64
#define BATCH 4
#define SLICES 8
#define NTHR 512
// fp16 pipeline: BK=64 (32 half2 words), A stage 128x36 words, B stage <=4608 words
#define STG 9216
#define SMEM_DYN (2*STG*4)   // 73728 bytes

// ---------------- scratch ----------------
__device__ float  g_K [NTOK*D];     // fp32 (g3 epilogue)
__device__ float  g_V [NTOK*D];     // fp32 (g3 epilogue)
__device__ float  g_Q [NTOK*D];     // fp32 (g7 residual)
__device__ float  g_GP[NTOK*HID];   // fp32 (g4 epilogue)
__device__ __half g_seqH[NTOK*D];
__device__ __half g_wkH[D*D], g_wvH[D*D], g_wqH[D*D];
__device__ __half g_w1H[D*HID];     // [d][hid]
__device__ __half g_w2H[HID*D];     // [hid][d]
__device__ __half g_KH [NTOK*D];
__device__ __half g_QH [NTOK*D];
__device__ __half g_AH [NTOK*HID];
__device__ __half g_dHH[NTOK*D];
__device__ __half g_dZH[NTOK*HID];
__device__ __half g_A2H[NTOK*HID];
__device__ __half g_w1fH[BATCH*D*HID];   // [d][hid] per bh
__device__ __half g_w2fH[BATCH*HID*D];   // [hid][d] per bh
__device__ float  g_lrv [BATCH*NC];
__device__ float  g_keep[BATCH*NC];
__device__ float  g_eta [BATCH*NC];
__device__ float  g_coef[BATCH*NC];
__device__ float  g_gfp[128*D];
__device__ float  g_gf [BATCH*D];
__device__ float  g_w1p[BATCH*SLICES*D*HID];
__device__ float  g_w2p[BATCH*SLICES*HID*D];

// ---------------- helpers ----------------
__device__ __forceinline__ float sigm(float x){ return 1.f/(1.f+expf(-x)); }
__device__ __forceinline__ float tanh_fast(float u){
    float e = __expf(2.f*u);
    return 1.f - __fdividef(2.f, e + 1.f);
}
__device__ __forceinline__ void gelu_both(float x, float& a, float& gp){
    const float c0 = 0.7978845608028654f, c1 = 0.044715f;
    float x2 = x*x;
    float t = tanh_fast(c0*x*(1.f + c1*x2));
    a  = 0.5f*x*(1.f + t);
    gp = 0.5f*(1.f + t) + 0.5f*x*(1.f - t*t)*c0*(1.f + 3.f*c1*x2);
}
__device__ __forceinline__ float gelu_f(float x){
    float t = tanh_fast(0.7978845608028654f*x*(1.f + 0.044715f*x*x));
    return 0.5f*x*(1.f + t);
}
__device__ __forceinline__ uint32_t h2pack(float lo, float hi){
    __half2 h = __floats2half2_rn(lo, hi);
    return *reinterpret_cast<uint32_t*>(&h);
}
__device__ __forceinline__ void mma16(float& c0, float& c1, float& c2, float& c3,
                                      uint32_t a0, uint32_t a1, uint32_t a2, uint32_t a3,
                                      uint32_t b0, uint32_t b1){
    asm volatile("mma.sync.aligned.m16n8k16.row.col.f32.f16.f16.f32 "
                 "{%0,%1,%2,%3}, {%4,%5,%6,%7}, {%8,%9}, {%0,%1,%2,%3};"
                 : "+f"(c0), "+f"(c1), "+f"(c2), "+f"(c3)
                 : "r"(a0), "r"(a1), "r"(a2), "r"(a3), "r"(b0), "r"(b1));
}

// ------------- fp16 warp-mma GEMM core: 128x128 tile, BK=64, 512 thr ------------
// 16 warps = 4(m) x 4(n); warp tile 32x32 = 2 mtiles x 4 ntiles of m16n8k16.
// A smem: [m][k2] stride 36 (k2 = k/2, half2-packed along k)
// B smem: BL=0 [k2][n] stride 136 (gmem [k][n], n contig)
//         BL=1 [n][k2] stride 36  (gmem [n][k], k contig)
// AL=0: A gmem [m][k] (k contig); AL=1: A gmem [k][m] (m contig) — free transpose.

template<int AL>
__device__ __forceinline__ void ldgA(const __half* __restrict__ Ag, int lda, int k0,
                                     int tid, uint4 ra[2]) {
    if (AL == 0) {
        #pragma unroll
        for (int j = 0; j < 2; j++) {
            int t = tid + j*NTHR;
            int m = t >> 3, q = t & 7;
            ra[j] = *reinterpret_cast<const uint4*>(Ag + (size_t)m*lda + k0 + q*8);
        }
    } else {
        int t2 = tid >> 4, d0 = (tid & 15)*8;
        const __half* p = Ag + (size_t)(k0 + 2*t2)*lda + d0;
        ra[0] = *reinterpret_cast<const uint4*>(p);
        ra[1] = *reinterpret_cast<const uint4*>(p + lda);
    }
}
template<int AL>
__device__ __forceinline__ void stsA(uint32_t* As, int tid, const uint4 ra[2]) {
    if (AL == 0) {
        #pragma unroll
        for (int j = 0; j < 2; j++) {
            int t = tid + j*NTHR;
            int m = t >> 3, q = t & 7;
            *reinterpret_cast<uint4*>(As + m*36 + q*4) = ra[j];
        }
    } else {
        int t2 = tid >> 4, d0 = (tid & 15)*8;
        const uint32_t* a = reinterpret_cast<const uint32_t*>(&ra[0]);
        const uint32_t* b = reinterpret_cast<const uint32_t*>(&ra[1]);
        #pragma unroll
        for (int j = 0; j < 4; j++) {
            As[(d0 + 2*j    )*36 + t2] = __byte_perm(a[j], b[j], 0x5410);
            As[(d0 + 2*j + 1)*36 + t2] = __byte_perm(a[j], b[j], 0x7632);
        }
    }
}
template<int BL>
__device__ __forceinline__ void ldgB(const __half* __restrict__ Bg, int ldb, int k0,
                                     int tid, uint4 rb[2]) {
    if (BL == 0) {
        int k2 = tid >> 4, n0 = (tid & 15)*8;
        const __half* p = Bg + (size_t)(k0 + 2*k2)*ldb + n0;
        rb[0] = *reinterpret_cast<const uint4*>(p);
        rb[1] = *reinterpret_cast<const uint4*>(p + ldb);
    } else {
        #pragma unroll
        for (int j = 0; j < 2; j++) {
            int t = tid + j*NTHR;
            int n = t >> 3, q = t & 7;
            rb[j] = *reinterpret_cast<const uint4*>(Bg + (size_t)n*ldb + k0 + q*8);
        }
    }
}
template<int BL>
__device__ __forceinline__ void stsB(uint32_t* Bs, int tid, const uint4 rb[2]) {
    if (BL == 0) {
        int k2 = tid >> 4, n0 = (tid & 15)*8;
        const uint32_t* a = reinterpret_cast<const uint32_t*>(&rb[0]);
        const uint32_t* b = reinterpret_cast<const uint32_t*>(&rb[1]);
        #pragma unroll
        for (int j = 0; j < 4; j++) {
            Bs[k2*136 + n0 + 2*j    ] = __byte_perm(a[j], b[j], 0x5410);
            Bs[k2*136 + n0 + 2*j + 1] = __byte_perm(a[j], b[j], 0x7632);
        }
    } else {
        #pragma unroll
        for (int j = 0; j < 2; j++) {
            int t = tid + j*NTHR;
            int n = t >> 3, q = t & 7;
            *reinterpret_cast<uint4*>(Bs + n*36 + q*4) = rb[j];
        }
    }
}

__device__ __forceinline__ void ldfA16(const uint32_t* As, int ks, int wm, int group, int tg,
                                       uint32_t af[2][4]) {
    #pragma unroll
    for (int mt = 0; mt < 2; mt++) {
        int r = wm*32 + mt*16 + group;
        int base = r*36 + ks*8 + tg;
        af[mt][0] = As[base];
        af[mt][1] = As[base + 8*36];
        af[mt][2] = As[base + 4];
        af[mt][3] = As[base + 8*36 + 4];
    }
}
template<int BL>
__device__ __forceinline__ void ldfB16(const uint32_t* Bs, int ks, int wn, int group, int tg,
                                       uint32_t bf[4][2]) {
    #pragma unroll
    for (int nt = 0; nt < 4; nt++) {
        int cb = wn*32 + nt*8 + group;
        if (BL == 0) {
            bf[nt][0] = Bs[(ks*8 + tg    )*136 + cb];
            bf[nt][1] = Bs[(ks*8 + tg + 4)*136 + cb];
        } else {
            bf[nt][0] = Bs[cb*36 + ks*8 + tg];
            bf[nt][1] = Bs[cb*36 + ks*8 + tg + 4];
        }
    }
}
__device__ __forceinline__ void mma_step(float acc[2][4][4],
                                         const uint32_t af[2][4], const uint32_t bf[4][2]) {
    #pragma unroll
    for (int nt = 0; nt < 4; nt++)
        #pragma unroll
        for (int mt = 0; mt < 2; mt++)
            mma16(acc[mt][nt][0], acc[mt][nt][1], acc[mt][nt][2], acc[mt][nt][3],
                  af[mt][0], af[mt][1], af[mt][2], af[mt][3], bf[nt][0], bf[nt][1]);
}

template<int AL, int BL, int NCH>   // NCH = K/64
__device__ __forceinline__ void mma_core(const __half* __restrict__ Ag, int lda,
                                         const __half* __restrict__ Bg, int ldb,
                                         float acc[2][4][4], uint32_t* smp) {
    const int tid = threadIdx.x;
    const int lane = tid & 31, group = lane >> 2, tg = lane & 3;
    const int wid = tid >> 5, wm = wid & 3, wn = wid >> 2;
    uint4 ra[2], rb[2];

    ldgA<AL>(Ag, lda, 0, tid, ra);
    ldgB<BL>(Bg, ldb, 0, tid, rb);
    stsA<AL>(smp, tid, ra);
    stsB<BL>(smp + 4608, tid, rb);
    __syncthreads();

    uint32_t af[2][2][4], bf[2][4][2];
    #pragma unroll 1
    for (int c = 0; c < NCH; c++) {
        const uint32_t* As = smp + (c & 1)*STG;
        const uint32_t* Bs = As + 4608;
        uint32_t* An = smp + ((c + 1) & 1)*STG;
        bool more = (c + 1 < NCH);
        if (more) {
            ldgA<AL>(Ag, lda, (c+1)*64, tid, ra);
            ldgB<BL>(Bg, ldb, (c+1)*64, tid, rb);
        }
        ldfA16(As, 0, wm, group, tg, af[0]); ldfB16<BL>(Bs, 0, wn, group, tg, bf[0]);
        ldfA16(As, 1, wm, group, tg, af[1]); ldfB16<BL>(Bs, 1, wn, group, tg, bf[1]);
        mma_step(acc, af[0], bf[0]);
        ldfA16(As, 2, wm, group, tg, af[0]); ldfB16<BL>(Bs, 2, wn, group, tg, bf[0]);
        mma_step(acc, af[1], bf[1]);
        if (more) { stsA<AL>(An, tid, ra); stsB<BL>(An + 4608, tid, rb); }
        ldfA16(As, 3, wm, group, tg, af[1]); ldfB16<BL>(Bs, 3, wn, group, tg, bf[1]);
        mma_step(acc, af[0], bf[0]);
        mma_step(acc, af[1], bf[1]);
        __syncthreads();
    }
}

// epilogue index helpers (row/col local to 128x128 tile)
#define ROW_OF(mt, h)  (wm*32 + (mt)*16 + group + 8*(h))
#define COL_OF(nt)     (wn*32 + (nt)*8 + 2*tg)

// ---------------- input conversion fp32 -> fp16 ----------------
__global__ void k_half(const float* __restrict__ seq, const float* __restrict__ wk,
                       const float* __restrict__ wv,  const float* __restrict__ wq,
                       const float* __restrict__ w1,  const float* __restrict__ w2) {
    int i4 = blockIdx.x*256 + threadIdx.x;
    const float4* src; __half* dst; int off;
    if      (i4 < 524288) { src = (const float4*)seq; dst = g_seqH; off = i4; }
    else if (i4 < 528384) { src = (const float4*)wk;  dst = g_wkH;  off = i4 - 524288; }
    else if (i4 < 532480) { src = (const float4*)wv;  dst = g_wvH;  off = i4 - 528384; }
    else if (i4 < 536576) { src = (const float4*)wq;  dst = g_wqH;  off = i4 - 532480; }
    else if (i4 < 552960) { src = (const float4*)w1;  dst = g_w1H;  off = i4 - 536576; }
    else if (i4 < 569344) { src = (const float4*)w2;  dst = g_w2H;  off = i4 - 552960; }
    else return;
    float4 v = src[off];
    uint2 o;
    o.x = h2pack(v.x, v.y);
    o.y = h2pack(v.z, v.w);
    *reinterpret_cast<uint2*>(dst + off*4) = o;
}

// ---------------- scalar kernels ----------------
__device__ __forceinline__ float bred128(float v){
    __shared__ float wr[4];
    #pragma unroll
    for (int o = 16; o > 0; o >>= 1) v += __shfl_down_sync(0xffffffffu, v, o);
    int tid = threadIdx.x;
    if ((tid & 31) == 0) wr[tid >> 5] = v;
    __syncthreads();
    float r = wr[0] + wr[1] + wr[2] + wr[3];
    __syncthreads();
    return r;
}
__global__ void k_dots(const float* __restrict__ seq,
                       const float* __restrict__ wlr,  const float* __restrict__ blr,
                       const float* __restrict__ wdec, const float* __restrict__ bdec,
                       const float* __restrict__ wmom, const float* __restrict__ bmom) {
    int b = blockIdx.x >> 6, c = blockIdx.x & 63;
    int tid = threadIdx.x;
    float x = seq[((size_t)b*4096 + c*64)*D + tid];
    float s1 = bred128(x*wlr[tid]);
    float s2 = bred128(x*wdec[tid]);
    float s3 = bred128(x*wmom[tid]);
    if (tid == 0) {
        g_lrv [b*NC + c] = sigm(s1 + blr[0]);
        g_keep[b*NC + c] = 1.f - sigm(s2 + bdec[0]);
        g_eta [b*NC + c] = sigm(s3 + bmom[0]);
    }
}
__global__ void k_coef() {
    int b = threadIdx.x;
    if (b >= BATCH) return;
    float Av = 1.f, Bv = 1.f;
    g_coef[b*NC + NC-1] = -g_lrv[b*NC + NC-1]*(2.f/128.f);
    for (int j = NC-2; j >= 0; j--) {
        Bv *= g_keep[b*NC + j+1];
        Av  = Bv + g_eta[b*NC + j+1]*Av;
        g_coef[b*NC + j] = -Av*g_lrv[b*NC + j]*(2.f/128.f);
    }
}

// ---------------- G1: K/V/Q = seq @ W ----------------
__global__ __launch_bounds__(NTHR) void g1_proj() {
    extern __shared__ uint32_t smp[];
    const __half* W = (blockIdx.z == 0) ? g_wkH : (blockIdx.z == 1 ? g_wvH : g_wqH);
    int row0 = blockIdx.x * 128;
    float acc[2][4][4] = {};
    mma_core<0,0,2>(g_seqH + (size_t)row0*D, D, W, D, acc, smp);
    const int tid = threadIdx.x, lane = tid & 31, group = lane >> 2, tg = lane & 3;
    const int wid = tid >> 5, wm = wid & 3, wn = wid >> 2;
    float* Of = (blockIdx.z == 0) ? g_K : (blockIdx.z == 1 ? g_V : g_Q);
    __half* Oh = (blockIdx.z == 0) ? g_KH : (blockIdx.z == 2 ? g_QH : nullptr);
    #pragma unroll
    for (int mt = 0; mt < 2; mt++)
        #pragma unroll
        for (int h = 0; h < 2; h++) {
            int tok = row0 + ROW_OF(mt, h);
            #pragma unroll
            for (int nt = 0; nt < 4; nt++) {
                int cc = COL_OF(nt);
                float v0 = acc[mt][nt][2*h], v1 = acc[mt][nt][2*h+1];
                *reinterpret_cast<float2*>(Of + (size_t)tok*D + cc) = make_float2(v0, v1);
                if (Oh)
                    *reinterpret_cast<uint32_t*>(Oh + (size_t)tok*D + cc) = h2pack(v0, v1);
            }
        }
}

// ---------------- G2: Z = K @ w1 -> gelu(half), gelu'(fp32) ----------------
__global__ __launch_bounds__(NTHR) void g2_zgelu() {
    extern __shared__ uint32_t smp[];
    int row0 = blockIdx.x*128, n0 = blockIdx.y*128;
    float acc[2][4][4] = {};
    mma_core<0,0,2>(g_KH + (size_t)row0*D, D, g_w1H + n0, HID, acc, smp);
    const int tid = threadIdx.x, lane = tid & 31, group = lane >> 2, tg = lane & 3;
    const int wid = tid >> 5, wm = wid & 3, wn = wid >> 2;
    #pragma unroll
    for (int mt = 0; mt < 2; mt++)
        #pragma unroll
        for (int h = 0; h < 2; h++) {
            int tok = row0 + ROW_OF(mt, h);
            size_t base = (size_t)tok*HID + n0;
            #pragma unroll
            for (int nt = 0; nt < 4; nt++) {
                int cc = COL_OF(nt);
                float a0, p0, a1, p1;
                gelu_both(acc[mt][nt][2*h],   a0, p0);
                gelu_both(acc[mt][nt][2*h+1], a1, p1);
                *reinterpret_cast<uint32_t*>(g_AH + base + cc) = h2pack(a0, a1);
                *reinterpret_cast<float2*>(g_GP + base + cc) = make_float2(p0, p1);
            }
        }
}

// ---------------- G3: H = A @ w2; rmsnorm bwd -> dH(half), dgamma partial -------
__global__ __launch_bounds__(NTHR) void g3_hback(const float* __restrict__ gamma) {
    extern __shared__ uint32_t smp[];
    __shared__ float gam[128];
    const int tid = threadIdx.x;
    if (tid < 128) gam[tid] = gamma[tid];
    int row0 = blockIdx.x * 128;
    float acc[2][4][4] = {};
    mma_core<0,0,8>(g_AH + (size_t)row0*HID, HID, g_w2H, D, acc, smp);
    const int lane = tid & 31, group = lane >> 2, tg = lane & 3;
    const int wid = tid >> 5, wm = wid & 3, wn = wid >> 2;
    float* rs = reinterpret_cast<float*>(smp);        // [4][128]
    float* cs = reinterpret_cast<float*>(smp) + 512;  // [4][128]

    #pragma unroll
    for (int mt = 0; mt < 2; mt++)
        #pragma unroll
        for (int h = 0; h < 2; h++) {
            float s = 0;
            #pragma unroll
            for (int nt = 0; nt < 4; nt++)
                s += acc[mt][nt][2*h]*acc[mt][nt][2*h] + acc[mt][nt][2*h+1]*acc[mt][nt][2*h+1];
            s += __shfl_xor_sync(0xffffffffu, s, 1);
            s += __shfl_xor_sync(0xffffffffu, s, 2);
            if (tg == 0) rs[wn*128 + ROW_OF(mt, h)] = s;
        }
    __syncthreads();
    float ir[2][2], cf[2][2];
    #pragma unroll
    for (int mt = 0; mt < 2; mt++)
        #pragma unroll
        for (int h = 0; h < 2; h++) {
            int r = ROW_OF(mt, h);
            float s = rs[r] + rs[128 + r] + rs[256 + r] + rs[384 + r];
            ir[mt][h] = rsqrtf(s*(1.f/128.f) + 1e-6f);
            int tok = row0 + r;
            cf[mt][h] = g_coef[(tok >> 12)*NC + ((tok & 4095) >> 6)];
        }
    __syncthreads();

    #pragma unroll
    for (int mt = 0; mt < 2; mt++)
        #pragma unroll
        for (int h = 0; h < 2; h++) {
            int r = ROW_OF(mt, h), tok = row0 + r;
            float irr = ir[mt][h], cfv = cf[mt][h];
            float dsum = 0;
            #pragma unroll
            for (int nt = 0; nt < 4; nt++) {
                int cc = COL_OF(nt);
                float2 kk = *reinterpret_cast<const float2*>(g_K + (size_t)tok*D + cc);
                float2 vv = *reinterpret_cast<const float2*>(g_V + (size_t)tok*D + cc);
                float hn0 = acc[mt][nt][2*h]*irr,   hn1 = acc[mt][nt][2*h+1]*irr;
                float dp0 = cfv*(hn0*gam[cc] + kk.x - vv.x);
                float dp1 = cfv*(hn1*gam[cc+1] + kk.y - vv.y);
                dsum += dp0*gam[cc]*hn0 + dp1*gam[cc+1]*hn1;
            }
            dsum += __shfl_xor_sync(0xffffffffu, dsum, 1);
            dsum += __shfl_xor_sync(0xffffffffu, dsum, 2);
            if (tg == 0) rs[wn*128 + r] = dsum;
        }
    __syncthreads();

    float colp[4][2] = {};
    #pragma unroll
    for (int mt = 0; mt < 2; mt++)
        #pragma unroll
        for (int h = 0; h < 2; h++) {
            int r = ROW_OF(mt, h), tok = row0 + r;
            float irr = ir[mt][h], cfv = cf[mt][h];
            float rd = (rs[r] + rs[128 + r] + rs[256 + r] + rs[384 + r])*(1.f/128.f);
            #pragma unroll
            for (int nt = 0; nt < 4; nt++) {
                int cc = COL_OF(nt);
                float2 kk = *reinterpret_cast<const float2*>(g_K + (size_t)tok*D + cc);
                float2 vv = *reinterpret_cast<const float2*>(g_V + (size_t)tok*D + cc);
                float hn0 = acc[mt][nt][2*h]*irr,   hn1 = acc[mt][nt][2*h+1]*irr;
                float dp0 = cfv*(hn0*gam[cc] + kk.x - vv.x);
                float dp1 = cfv*(hn1*gam[cc+1] + kk.y - vv.y);
                float o0 = irr*(dp0*gam[cc]   - hn0*rd);
                float o1 = irr*(dp1*gam[cc+1] - hn1*rd);
                *reinterpret_cast<uint32_t*>(g_dHH + (size_t)tok*D + cc) = h2pack(o0, o1);
                colp[nt][0] += dp0*hn0;
                colp[nt][1] += dp1*hn1;
            }
        }
    __syncthreads();
    #pragma unroll
    for (int nt = 0; nt < 4; nt++)
        #pragma unroll
        for (int j = 0; j < 2; j++) {
            float v = colp[nt][j];
            v += __shfl_xor_sync(0xffffffffu, v, 4);
            v += __shfl_xor_sync(0xffffffffu, v, 8);
            v += __shfl_xor_sync(0xffffffffu, v, 16);
            if (group == 0) cs[wm*128 + COL_OF(nt) + j] = v;
        }
    __syncthreads();
    if (tid < 128) {
        float s = cs[tid] + cs[128 + tid] + cs[256 + tid] + cs[384 + tid];
        g_gfp[blockIdx.x*128 + tid] = s;
    }
}

// ---------------- G4: dZ = (dH @ w2^T) * GP ----------------
__global__ __launch_bounds__(NTHR) void g4_da() {
    extern __shared__ uint32_t smp[];
    int row0 = blockIdx.x*128, n0 = blockIdx.y*128;
    float acc[2][4][4] = {};
    mma_core<0,1,2>(g_dHH + (size_t)row0*D, D, g_w2H + (size_t)n0*D, D, acc, smp);
    const int tid = threadIdx.x, lane = tid & 31, group = lane >> 2, tg = lane & 3;
    const int wid = tid >> 5, wm = wid & 3, wn = wid >> 2;
    #pragma unroll
    for (int mt = 0; mt < 2; mt++)
        #pragma unroll
        for (int h = 0; h < 2; h++) {
            int tok = row0 + ROW_OF(mt, h);
            size_t base = (size_t)tok*HID + n0;
            #pragma unroll
            for (int nt = 0; nt < 4; nt++) {
                int cc = COL_OF(nt);
                float2 gp = *reinterpret_cast<const float2*>(g_GP + base + cc);
                *reinterpret_cast<uint32_t*>(g_dZH + base + cc) =
                    h2pack(acc[mt][nt][2*h]*gp.x, acc[mt][nt][2*h+1]*gp.y);
            }
        }
}

// ---------------- G5 merged: y=0 w1p = K^T@dZ ; y=1 w2p = A^T@dH ----------------
__global__ __launch_bounds__(NTHR) void g5_wp() {
    extern __shared__ uint32_t smp[];
    int z = blockIdx.z, bh = z >> 3, sl = z & 7;
    int t0 = bh*4096 + sl*512;
    const __half* Ag; const __half* Bg; int lda, ldb;
    if (blockIdx.y == 0) {
        Ag = g_KH + (size_t)t0*D;                    lda = D;
        Bg = g_dZH + (size_t)t0*HID + blockIdx.x*128; ldb = HID;
    } else {
        Ag = g_AH + (size_t)t0*HID + blockIdx.x*128; lda = HID;
        Bg = g_dHH + (size_t)t0*D;                   ldb = D;
    }
    float acc[2][4][4] = {};
    mma_core<1,0,8>(Ag, lda, Bg, ldb, acc, smp);
    const int tid = threadIdx.x, lane = tid & 31, group = lane >> 2, tg = lane & 3;
    const int wid = tid >> 5, wm = wid & 3, wn = wid >> 2;
    if (blockIdx.y == 0) {
        float* C = g_w1p + (size_t)z*(D*HID);
        int n0 = blockIdx.x * 128;
        #pragma unroll
        for (int mt = 0; mt < 2; mt++)
            #pragma unroll
            for (int h = 0; h < 2; h++) {
                int r = ROW_OF(mt, h);
                #pragma unroll
                for (int nt = 0; nt < 4; nt++)
                    *reinterpret_cast<float2*>(C + (size_t)r*HID + n0 + COL_OF(nt)) =
                        make_float2(acc[mt][nt][2*h], acc[mt][nt][2*h+1]);
            }
    } else {
        float* C = g_w2p + (size_t)z*(HID*D);
        int m0 = blockIdx.x * 128;
        #pragma unroll
        for (int mt = 0; mt < 2; mt++)
            #pragma unroll
            for (int h = 0; h < 2; h++) {
                int r = m0 + ROW_OF(mt, h);
                #pragma unroll
                for (int nt = 0; nt < 4; nt++)
                    *reinterpret_cast<float2*>(C + (size_t)r*D + COL_OF(nt)) =
                        make_float2(acc[mt][nt][2*h], acc[mt][nt][2*h+1]);
            }
    }
}

// ---------------- reduce split-K partials (fp32) -> half finals + dgamma --------
__global__ void k_reduce() {
    int i = blockIdx.x*256 + threadIdx.x;
    if (i < BATCH*D*HID) {
        int bh = i >> 16, off = i & 65535;
        float s1 = 0, s2 = 0;
        #pragma unroll
        for (int s = 0; s < SLICES; s++) {
            s1 += g_w1p[(size_t)(bh*SLICES + s)*(D*HID) + off];
            s2 += g_w2p[(size_t)(bh*SLICES + s)*(HID*D) + off];
        }
        g_w1fH[i] = __float2half_rn(s1);
        g_w2fH[i] = __float2half_rn(s2);
    }
    if (i < BATCH*D) {
        int bh = i >> 7, col = i & 127;
        float s = 0;
        #pragma unroll
        for (int q = 0; q < 32; q++) s += g_gfp[(bh*32 + q)*128 + col];
        g_gf[i] = s;
    }
}

// ---------------- G6: A2 = gelu(Q @ w1f) ----------------
__global__ __launch_bounds__(NTHR) void g6_z2() {
    extern __shared__ uint32_t smp[];
    int row0 = blockIdx.x*128, n0 = blockIdx.y*128;
    int bh = row0 >> 12;
    float acc[2][4][4] = {};
    mma_core<0,0,2>(g_QH + (size_t)row0*D, D, g_w1fH + (size_t)bh*(D*HID) + n0, HID, acc, smp);
    const int tid = threadIdx.x, lane = tid & 31, group = lane >> 2, tg = lane & 3;
    const int wid = tid >> 5, wm = wid & 3, wn = wid >> 2;
    #pragma unroll
    for (int mt = 0; mt < 2; mt++)
        #pragma unroll
        for (int h = 0; h < 2; h++) {
            int tok = row0 + ROW_OF(mt, h);
            size_t base = (size_t)tok*HID + n0;
            #pragma unroll
            for (int nt = 0; nt < 4; nt++) {
                int cc = COL_OF(nt);
                *reinterpret_cast<uint32_t*>(g_A2H + base + cc) =
                    h2pack(gelu_f(acc[mt][nt][2*h]), gelu_f(acc[mt][nt][2*h+1]));
            }
        }
}

// ---------------- G7: out = rmsnorm(A2 @ w2f)*gf + Q ----------------
__global__ __launch_bounds__(NTHR) void g7_out(float* __restrict__ out) {
    extern __shared__ uint32_t smp[];
    __shared__ float gfs[128];
    const int tid = threadIdx.x;
    int row0 = blockIdx.x * 128;
    int bh = row0 >> 12;
    if (tid < 128) gfs[tid] = g_gf[bh*D + tid];
    float acc[2][4][4] = {};
    mma_core<0,0,8>(g_A2H + (size_t)row0*HID, HID, g_w2fH + (size_t)bh*(HID*D), D, acc, smp);
    const int lane = tid & 31, group = lane >> 2, tg = lane & 3;
    const int wid = tid >> 5, wm = wid & 3, wn = wid >> 2;
    float* rs = reinterpret_cast<float*>(smp);  // [4][128]
    #pragma unroll
    for (int mt = 0; mt < 2; mt++)
        #pragma unroll
        for (int h = 0; h < 2; h++) {
            float s = 0;
            #pragma unroll
            for (int nt = 0; nt < 4; nt++)
                s += acc[mt][nt][2*h]*acc[mt][nt][2*h] + acc[mt][nt][2*h+1]*acc[mt][nt][2*h+1];
            s += __shfl_xor_sync(0xffffffffu, s, 1);
            s += __shfl_xor_sync(0xffffffffu, s, 2);
            if (tg == 0) rs[wn*128 + ROW_OF(mt, h)] = s;
        }
    __syncthreads();
    #pragma unroll
    for (int mt = 0; mt < 2; mt++)
        #pragma unroll
        for (int h = 0; h < 2; h++) {
            int r = ROW_OF(mt, h), tok = row0 + r;
            float s = rs[r] + rs[128 + r] + rs[256 + r] + rs[384 + r];
            float irr = rsqrtf(s*(1.f/128.f) + 1e-6f);
            #pragma unroll
            for (int nt = 0; nt < 4; nt++) {
                int cc = COL_OF(nt);
                float2 qq = *reinterpret_cast<const float2*>(g_Q + (size_t)tok*D + cc);
                *reinterpret_cast<float2*>(out + (size_t)tok*D + cc) =
                    make_float2(acc[mt][nt][2*h]*irr*gfs[cc] + qq.x,
                                acc[mt][nt][2*h+1]*irr*gfs[cc+1] + qq.y);
            }
        }
}

// ---------------- launch ----------------
extern "C" void kernel_launch(void* const* d_in, const int* in_sizes, int n_in,
                              void* d_out, int out_size) {
    (void)in_sizes; (void)n_in; (void)out_size;
    const float* seq  = (const float*)d_in[0];
    const float* wk   = (const float*)d_in[1];
    const float* wv   = (const float*)d_in[2];
    const float* wq   = (const float*)d_in[3];
    const float* wlr  = (const float*)d_in[4];
    const float* blr  = (const float*)d_in[5];
    const float* wdec = (const float*)d_in[6];
    const float* bdec = (const float*)d_in[7];
    const float* wmom = (const float*)d_in[8];
    const float* bmom = (const float*)d_in[9];
    const float* gamma= (const float*)d_in[10];
    const float* w1   = (const float*)d_in[11];
    const float* w2   = (const float*)d_in[12];
    float* out = (float*)d_out;

    cudaFuncSetAttribute(g1_proj,  cudaFuncAttributeMaxDynamicSharedMemorySize, SMEM_DYN);
    cudaFuncSetAttribute(g2_zgelu, cudaFuncAttributeMaxDynamicSharedMemorySize, SMEM_DYN);
    cudaFuncSetAttribute(g3_hback, cudaFuncAttributeMaxDynamicSharedMemorySize, SMEM_DYN);
    cudaFuncSetAttribute(g4_da,    cudaFuncAttributeMaxDynamicSharedMemorySize, SMEM_DYN);
    cudaFuncSetAttribute(g5_wp,    cudaFuncAttributeMaxDynamicSharedMemorySize, SMEM_DYN);
    cudaFuncSetAttribute(g6_z2,    cudaFuncAttributeMaxDynamicSharedMemorySize, SMEM_DYN);
    cudaFuncSetAttribute(g7_out,   cudaFuncAttributeMaxDynamicSharedMemorySize, SMEM_DYN);

    k_half  <<<2224, 256>>>(seq, wk, wv, wq, w1, w2);
    k_dots  <<<BATCH*NC, 128>>>(seq, wlr, blr, wdec, bdec, wmom, bmom);
    k_coef  <<<1, 32>>>();
    g1_proj <<<dim3(NTOK/128, 1, 3), NTHR, SMEM_DYN>>>();
    g2_zgelu<<<dim3(NTOK/128, HID/128), NTHR, SMEM_DYN>>>();
    g3_hback<<<NTOK/128, NTHR, SMEM_DYN>>>(gamma);
    g4_da   <<<dim3(NTOK/128, HID/128), NTHR, SMEM_DYN>>>();
    g5_wp   <<<dim3(HID/128, 2, BATCH*SLICES), NTHR, SMEM_DYN>>>();
    k_reduce<<<(BATCH*D*HID)/256, 256>>>();
    g6_z2   <<<dim3(NTOK/128, HID/128), NTHR, SMEM_DYN>>>();
    g7_out  <<<NTOK/128, NTHR, SMEM_DYN>>>(out);
}

// round 8
// speedup vs baseline: 1.7706x; 1.3111x over previous
#include <cuda_runtime.h>
#include <cuda_fp16.h>
#include <stdint.h>
#include <math.h>

// dims: b=4, n=4096, d=128, hid=512, CHUNK=64
#define NTOK 16384
#define D 128
#define HID 512
#define NC 64
#define BATCH 4
#define SLICES 8
#define NTHR 512
// BK=64 halves. Stage = A tile 16KB + B tile 16KB = 32KB; 3 stages.
#define STG_BYTES 32768
#define SMEM_DYN (3*STG_BYTES)   // 98304

// ---------------- scratch ----------------
__device__ float  g_K [NTOK*D];
__device__ float  g_V [NTOK*D];
__device__ float  g_Q [NTOK*D];
__device__ float  g_GP[NTOK*HID];
__device__ __half g_seqH[NTOK*D];
__device__ __half g_wkH[D*D], g_wvH[D*D], g_wqH[D*D];
__device__ __half g_w1H[D*HID];
__device__ __half g_w2H[HID*D];
__device__ __half g_KH [NTOK*D];
__device__ __half g_QH [NTOK*D];
__device__ __half g_AH [NTOK*HID];
__device__ __half g_dHH[NTOK*D];
__device__ __half g_dZH[NTOK*HID];
__device__ __half g_A2H[NTOK*HID];
__device__ __half g_w1fH[BATCH*D*HID];
__device__ __half g_w2fH[BATCH*HID*D];
__device__ float  g_lrv [BATCH*NC];
__device__ float  g_keep[BATCH*NC];
__device__ float  g_eta [BATCH*NC];
__device__ float  g_coef[BATCH*NC];
__device__ float  g_gfp[128*D];
__device__ float  g_gf [BATCH*D];
__device__ float  g_w1p[BATCH*SLICES*D*HID];
__device__ float  g_w2p[BATCH*SLICES*HID*D];

// ---------------- helpers ----------------
__device__ __forceinline__ float sigm(float x){ return 1.f/(1.f+expf(-x)); }
__device__ __forceinline__ float tanh_fast(float u){
    float e = __expf(2.f*u);
    return 1.f - __fdividef(2.f, e + 1.f);
}
__device__ __forceinline__ void gelu_both(float x, float& a, float& gp){
    const float c0 = 0.7978845608028654f, c1 = 0.044715f;
    float x2 = x*x;
    float t = tanh_fast(c0*x*(1.f + c1*x2));
    a  = 0.5f*x*(1.f + t);
    gp = 0.5f*(1.f + t) + 0.5f*x*(1.f - t*t)*c0*(1.f + 3.f*c1*x2);
}
__device__ __forceinline__ float gelu_f(float x){
    float t = tanh_fast(0.7978845608028654f*x*(1.f + 0.044715f*x*x));
    return 0.5f*x*(1.f + t);
}
__device__ __forceinline__ uint32_t h2pack(float lo, float hi){
    __half2 h = __floats2half2_rn(lo, hi);
    return *reinterpret_cast<uint32_t*>(&h);
}
__device__ __forceinline__ void mma16(float& c0, float& c1, float& c2, float& c3,
                                      uint32_t a0, uint32_t a1, uint32_t a2, uint32_t a3,
                                      uint32_t b0, uint32_t b1){
    asm volatile("mma.sync.aligned.m16n8k16.row.col.f32.f16.f16.f32 "
                 "{%0,%1,%2,%3}, {%4,%5,%6,%7}, {%8,%9}, {%0,%1,%2,%3};"
                 : "+f"(c0), "+f"(c1), "+f"(c2), "+f"(c3)
                 : "r"(a0), "r"(a1), "r"(a2), "r"(a3), "r"(b0), "r"(b1));
}
__device__ __forceinline__ uint32_t smem_u32(const void* p){
    uint32_t a;
    asm("{ .reg .u64 t; cvta.to.shared.u64 t, %1; cvt.u32.u64 %0, t; }" : "=r"(a) : "l"(p));
    return a;
}
__device__ __forceinline__ void cp16(uint32_t dst, const void* src){
    asm volatile("cp.async.cg.shared.global [%0], [%1], 16;" :: "r"(dst), "l"(src));
}
#define CP_COMMIT() asm volatile("cp.async.commit_group;" ::: "memory")
#define CP_WAIT1()  asm volatile("cp.async.wait_group 1;" ::: "memory")
__device__ __forceinline__ void ldm_x4(uint32_t& r0, uint32_t& r1, uint32_t& r2, uint32_t& r3,
                                       uint32_t a){
    asm volatile("ldmatrix.sync.aligned.m8n8.x4.shared.b16 {%0,%1,%2,%3}, [%4];"
                 : "=r"(r0), "=r"(r1), "=r"(r2), "=r"(r3) : "r"(a));
}
__device__ __forceinline__ void ldm_x4t(uint32_t& r0, uint32_t& r1, uint32_t& r2, uint32_t& r3,
                                        uint32_t a){
    asm volatile("ldmatrix.sync.aligned.m8n8.x4.trans.shared.b16 {%0,%1,%2,%3}, [%4];"
                 : "=r"(r0), "=r"(r1), "=r"(r2), "=r"(r3) : "r"(a));
}

// ------------- cp.async tile copies (raw gmem layout, XOR-swizzled 16B chunks) --
// AL=0: A gmem [m][k] -> smem rows m (128 x 8 chunks)
// AL=1: A gmem [k][m] -> smem rows k (64 x 16 chunks)
// BL=0: B gmem [k][n] -> smem rows k (64 x 16 chunks)
// BL=1: B gmem [n][k] -> smem rows n (128 x 8 chunks)
template<int AL>
__device__ __forceinline__ void cpA(uint32_t dstb, const __half* __restrict__ Ag, int lda,
                                    int k0, int tid){
    #pragma unroll
    for (int j = 0; j < 2; j++) {
        int i = tid + j*NTHR;
        if (AL == 0) { int m = i >> 3, c = i & 7;
            cp16(dstb + (uint32_t)(m*128 + ((c ^ (m & 7)) << 4)),
                 Ag + (size_t)m*lda + k0 + c*8); }
        else         { int r = i >> 4, c = i & 15;
            cp16(dstb + (uint32_t)(r*256 + ((c ^ (r & 7)) << 4)),
                 Ag + (size_t)(k0 + r)*lda + c*8); }
    }
}
template<int BL>
__device__ __forceinline__ void cpB(uint32_t dstb, const __half* __restrict__ Bg, int ldb,
                                    int k0, int tid){
    #pragma unroll
    for (int j = 0; j < 2; j++) {
        int i = tid + j*NTHR;
        if (BL == 0) { int r = i >> 4, c = i & 15;
            cp16(dstb + (uint32_t)(r*256 + ((c ^ (r & 7)) << 4)),
                 Bg + (size_t)(k0 + r)*ldb + c*8); }
        else         { int n = i >> 3, c = i & 7;
            cp16(dstb + (uint32_t)(n*128 + ((c ^ (n & 7)) << 4)),
                 Bg + (size_t)n*ldb + k0 + c*8); }
    }
}

// ------------- ldmatrix fragment loads ------------------------------------------
template<int AL>
__device__ __forceinline__ void ldfA(uint32_t Ab, int ks, int wm, int lane,
                                     uint32_t af[2][4]){
    int rl = lane & 7;
    if (AL == 0) {
        int half = (lane >> 3) & 1, kc = lane >> 4;
        #pragma unroll
        for (int mt = 0; mt < 2; mt++) {
            int row = wm*32 + mt*16 + half*8 + rl;
            uint32_t addr = Ab + row*128 + ((((ks << 1) | kc) ^ rl) << 4);
            ldm_x4(af[mt][0], af[mt][1], af[mt][2], af[mt][3], addr);
        }
    } else {
        int sel = (lane >> 3) & 1, kh = lane >> 4;
        int row = 16*ks + 8*kh + rl;
        #pragma unroll
        for (int mt = 0; mt < 2; mt++) {
            int cm = wm*4 + mt*2 + sel;
            uint32_t addr = Ab + row*256 + (((uint32_t)(cm ^ rl)) << 4);
            ldm_x4t(af[mt][0], af[mt][1], af[mt][2], af[mt][3], addr);
        }
    }
}
template<int BL>
__device__ __forceinline__ void ldfB(uint32_t Bb, int ks, int wn, int lane,
                                     uint32_t bf[4][2]){
    int rl = lane & 7;
    if (BL == 1) {
        int half = (lane >> 3) & 1, kc = lane >> 4;
        #pragma unroll
        for (int ntp = 0; ntp < 2; ntp++) {
            int row = wn*32 + ntp*16 + half*8 + rl;
            uint32_t addr = Bb + row*128 + ((((ks << 1) | kc) ^ rl) << 4);
            ldm_x4(bf[2*ntp][0], bf[2*ntp+1][0], bf[2*ntp][1], bf[2*ntp+1][1], addr);
        }
    } else {
        int sel = (lane >> 3) & 1, kh = lane >> 4;
        int row = 16*ks + 8*kh + rl;
        #pragma unroll
        for (int ntp = 0; ntp < 2; ntp++) {
            int cn = wn*4 + ntp*2 + sel;
            uint32_t addr = Bb + row*256 + (((uint32_t)(cn ^ rl)) << 4);
            ldm_x4t(bf[2*ntp][0], bf[2*ntp+1][0], bf[2*ntp][1], bf[2*ntp+1][1], addr);
        }
    }
}
__device__ __forceinline__ void mma_step(float acc[2][4][4],
                                         const uint32_t af[2][4], const uint32_t bf[4][2]) {
    #pragma unroll
    for (int nt = 0; nt < 4; nt++)
        #pragma unroll
        for (int mt = 0; mt < 2; mt++)
            mma16(acc[mt][nt][0], acc[mt][nt][1], acc[mt][nt][2], acc[mt][nt][3],
                  af[mt][0], af[mt][1], af[mt][2], af[mt][3], bf[nt][0], bf[nt][1]);
}

// ------------- 3-stage cp.async pipelined GEMM core -----------------------------
template<int AL, int BL, int NCH>   // NCH = K/64
__device__ __forceinline__ void mma_core(const __half* __restrict__ Ag, int lda,
                                         const __half* __restrict__ Bg, int ldb,
                                         float acc[2][4][4], char* smraw) {
    const int tid = threadIdx.x, lane = tid & 31;
    const int wid = tid >> 5, wm = wid & 3, wn = wid >> 2;
    const uint32_t sb = smem_u32(smraw);

    cpA<AL>(sb, Ag, lda, 0, tid);
    cpB<BL>(sb + 16384u, Bg, ldb, 0, tid);
    CP_COMMIT();
    if (NCH > 1) {
        cpA<AL>(sb + STG_BYTES, Ag, lda, 64, tid);
        cpB<BL>(sb + STG_BYTES + 16384u, Bg, ldb, 64, tid);
    }
    CP_COMMIT();

    uint32_t af[2][4], bf[4][2];
    int cur = 0, nxt2 = 2;
    #pragma unroll 1
    for (int c = 0; c < NCH; c++) {
        CP_WAIT1();
        __syncthreads();
        if (c + 2 < NCH) {
            uint32_t ns = sb + (uint32_t)nxt2*STG_BYTES;
            cpA<AL>(ns, Ag, lda, (c+2)*64, tid);
            cpB<BL>(ns + 16384u, Bg, ldb, (c+2)*64, tid);
        }
        CP_COMMIT();
        uint32_t Ab = sb + (uint32_t)cur*STG_BYTES;
        uint32_t Bb = Ab + 16384u;
        #pragma unroll
        for (int ks = 0; ks < 4; ks++) {
            ldfA<AL>(Ab, ks, wm, lane, af);
            ldfB<BL>(Bb, ks, wn, lane, bf);
            mma_step(acc, af, bf);
        }
        cur++;  if (cur == 3) cur = 0;
        nxt2++; if (nxt2 == 3) nxt2 = 0;
    }
    __syncthreads();
}

// epilogue index helpers (row/col local to 128x128 tile)
#define ROW_OF(mt, h)  (wm*32 + (mt)*16 + group + 8*(h))
#define COL_OF(nt)     (wn*32 + (nt)*8 + 2*tg)

// ---------------- input conversion fp32 -> fp16 ----------------
__global__ void k_half(const float* __restrict__ seq, const float* __restrict__ wk,
                       const float* __restrict__ wv,  const float* __restrict__ wq,
                       const float* __restrict__ w1,  const float* __restrict__ w2) {
    int i4 = blockIdx.x*256 + threadIdx.x;
    const float4* src; __half* dst; int off;
    if      (i4 < 524288) { src = (const float4*)seq; dst = g_seqH; off = i4; }
    else if (i4 < 528384) { src = (const float4*)wk;  dst = g_wkH;  off = i4 - 524288; }
    else if (i4 < 532480) { src = (const float4*)wv;  dst = g_wvH;  off = i4 - 528384; }
    else if (i4 < 536576) { src = (const float4*)wq;  dst = g_wqH;  off = i4 - 532480; }
    else if (i4 < 552960) { src = (const float4*)w1;  dst = g_w1H;  off = i4 - 536576; }
    else if (i4 < 569344) { src = (const float4*)w2;  dst = g_w2H;  off = i4 - 552960; }
    else return;
    float4 v = src[off];
    uint2 o;
    o.x = h2pack(v.x, v.y);
    o.y = h2pack(v.z, v.w);
    *reinterpret_cast<uint2*>(dst + off*4) = o;
}

// ---------------- scalar kernels ----------------
__device__ __forceinline__ float bred128(float v){
    __shared__ float wr[4];
    #pragma unroll
    for (int o = 16; o > 0; o >>= 1) v += __shfl_down_sync(0xffffffffu, v, o);
    int tid = threadIdx.x;
    if ((tid & 31) == 0) wr[tid >> 5] = v;
    __syncthreads();
    float r = wr[0] + wr[1] + wr[2] + wr[3];
    __syncthreads();
    return r;
}
__global__ void k_dots(const float* __restrict__ seq,
                       const float* __restrict__ wlr,  const float* __restrict__ blr,
                       const float* __restrict__ wdec, const float* __restrict__ bdec,
                       const float* __restrict__ wmom, const float* __restrict__ bmom) {
    int b = blockIdx.x >> 6, c = blockIdx.x & 63;
    int tid = threadIdx.x;
    float x = seq[((size_t)b*4096 + c*64)*D + tid];
    float s1 = bred128(x*wlr[tid]);
    float s2 = bred128(x*wdec[tid]);
    float s3 = bred128(x*wmom[tid]);
    if (tid == 0) {
        g_lrv [b*NC + c] = sigm(s1 + blr[0]);
        g_keep[b*NC + c] = 1.f - sigm(s2 + bdec[0]);
        g_eta [b*NC + c] = sigm(s3 + bmom[0]);
    }
}
__global__ void k_coef() {
    int b = threadIdx.x;
    if (b >= BATCH) return;
    float Av = 1.f, Bv = 1.f;
    g_coef[b*NC + NC-1] = -g_lrv[b*NC + NC-1]*(2.f/128.f);
    for (int j = NC-2; j >= 0; j--) {
        Bv *= g_keep[b*NC + j+1];
        Av  = Bv + g_eta[b*NC + j+1]*Av;
        g_coef[b*NC + j] = -Av*g_lrv[b*NC + j]*(2.f/128.f);
    }
}

// ---------------- G1: K/V/Q = seq @ W ----------------
__global__ __launch_bounds__(NTHR, 2) void g1_proj() {
    extern __shared__ char smraw[];
    const __half* W = (blockIdx.z == 0) ? g_wkH : (blockIdx.z == 1 ? g_wvH : g_wqH);
    int row0 = blockIdx.x * 128;
    float acc[2][4][4] = {};
    mma_core<0,0,2>(g_seqH + (size_t)row0*D, D, W, D, acc, smraw);
    const int tid = threadIdx.x, lane = tid & 31, group = lane >> 2, tg = lane & 3;
    const int wid = tid >> 5, wm = wid & 3, wn = wid >> 2;
    float* Of = (blockIdx.z == 0) ? g_K : (blockIdx.z == 1 ? g_V : g_Q);
    __half* Oh = (blockIdx.z == 0) ? g_KH : (blockIdx.z == 2 ? g_QH : nullptr);
    #pragma unroll
    for (int mt = 0; mt < 2; mt++)
        #pragma unroll
        for (int h = 0; h < 2; h++) {
            int tok = row0 + ROW_OF(mt, h);
            #pragma unroll
            for (int nt = 0; nt < 4; nt++) {
                int cc = COL_OF(nt);
                float v0 = acc[mt][nt][2*h], v1 = acc[mt][nt][2*h+1];
                *reinterpret_cast<float2*>(Of + (size_t)tok*D + cc) = make_float2(v0, v1);
                if (Oh)
                    *reinterpret_cast<uint32_t*>(Oh + (size_t)tok*D + cc) = h2pack(v0, v1);
            }
        }
}

// ---------------- G2: Z = K @ w1 -> gelu(half), gelu'(fp32) ----------------
__global__ __launch_bounds__(NTHR, 2) void g2_zgelu() {
    extern __shared__ char smraw[];
    int row0 = blockIdx.x*128, n0 = blockIdx.y*128;
    float acc[2][4][4] = {};
    mma_core<0,0,2>(g_KH + (size_t)row0*D, D, g_w1H + n0, HID, acc, smraw);
    const int tid = threadIdx.x, lane = tid & 31, group = lane >> 2, tg = lane & 3;
    const int wid = tid >> 5, wm = wid & 3, wn = wid >> 2;
    #pragma unroll
    for (int mt = 0; mt < 2; mt++)
        #pragma unroll
        for (int h = 0; h < 2; h++) {
            int tok = row0 + ROW_OF(mt, h);
            size_t base = (size_t)tok*HID + n0;
            #pragma unroll
            for (int nt = 0; nt < 4; nt++) {
                int cc = COL_OF(nt);
                float a0, p0, a1, p1;
                gelu_both(acc[mt][nt][2*h],   a0, p0);
                gelu_both(acc[mt][nt][2*h+1], a1, p1);
                *reinterpret_cast<uint32_t*>(g_AH + base + cc) = h2pack(a0, a1);
                *reinterpret_cast<float2*>(g_GP + base + cc) = make_float2(p0, p1);
            }
        }
}

// ---------------- G3: H = A @ w2; rmsnorm bwd -> dH(half), dgamma partial -------
__global__ __launch_bounds__(NTHR) void g3_hback(const float* __restrict__ gamma) {
    extern __shared__ char smraw[];
    __shared__ float gam[128];
    const int tid = threadIdx.x;
    if (tid < 128) gam[tid] = gamma[tid];
    int row0 = blockIdx.x * 128;
    float acc[2][4][4] = {};
    mma_core<0,0,8>(g_AH + (size_t)row0*HID, HID, g_w2H, D, acc, smraw);
    const int lane = tid & 31, group = lane >> 2, tg = lane & 3;
    const int wid = tid >> 5, wm = wid & 3, wn = wid >> 2;
    float* rs = reinterpret_cast<float*>(smraw);        // [4][128]
    float* cs = reinterpret_cast<float*>(smraw) + 512;  // [4][128]

    #pragma unroll
    for (int mt = 0; mt < 2; mt++)
        #pragma unroll
        for (int h = 0; h < 2; h++) {
            float s = 0;
            #pragma unroll
            for (int nt = 0; nt < 4; nt++)
                s += acc[mt][nt][2*h]*acc[mt][nt][2*h] + acc[mt][nt][2*h+1]*acc[mt][nt][2*h+1];
            s += __shfl_xor_sync(0xffffffffu, s, 1);
            s += __shfl_xor_sync(0xffffffffu, s, 2);
            if (tg == 0) rs[wn*128 + ROW_OF(mt, h)] = s;
        }
    __syncthreads();
    float ir[2][2], cf[2][2];
    #pragma unroll
    for (int mt = 0; mt < 2; mt++)
        #pragma unroll
        for (int h = 0; h < 2; h++) {
            int r = ROW_OF(mt, h);
            float s = rs[r] + rs[128 + r] + rs[256 + r] + rs[384 + r];
            ir[mt][h] = rsqrtf(s*(1.f/128.f) + 1e-6f);
            int tok = row0 + r;
            cf[mt][h] = g_coef[(tok >> 12)*NC + ((tok & 4095) >> 6)];
        }
    __syncthreads();

    #pragma unroll
    for (int mt = 0; mt < 2; mt++)
        #pragma unroll
        for (int h = 0; h < 2; h++) {
            int r = ROW_OF(mt, h), tok = row0 + r;
            float irr = ir[mt][h], cfv = cf[mt][h];
            float dsum = 0;
            #pragma unroll
            for (int nt = 0; nt < 4; nt++) {
                int cc = COL_OF(nt);
                float2 kk = *reinterpret_cast<const float2*>(g_K + (size_t)tok*D + cc);
                float2 vv = *reinterpret_cast<const float2*>(g_V + (size_t)tok*D + cc);
                float hn0 = acc[mt][nt][2*h]*irr,   hn1 = acc[mt][nt][2*h+1]*irr;
                float dp0 = cfv*(hn0*gam[cc] + kk.x - vv.x);
                float dp1 = cfv*(hn1*gam[cc+1] + kk.y - vv.y);
                dsum += dp0*gam[cc]*hn0 + dp1*gam[cc+1]*hn1;
            }
            dsum += __shfl_xor_sync(0xffffffffu, dsum, 1);
            dsum += __shfl_xor_sync(0xffffffffu, dsum, 2);
            if (tg == 0) rs[wn*128 + r] = dsum;
        }
    __syncthreads();

    float colp[4][2] = {};
    #pragma unroll
    for (int mt = 0; mt < 2; mt++)
        #pragma unroll
        for (int h = 0; h < 2; h++) {
            int r = ROW_OF(mt, h), tok = row0 + r;
            float irr = ir[mt][h], cfv = cf[mt][h];
            float rd = (rs[r] + rs[128 + r] + rs[256 + r] + rs[384 + r])*(1.f/128.f);
            #pragma unroll
            for (int nt = 0; nt < 4; nt++) {
                int cc = COL_OF(nt);
                float2 kk = *reinterpret_cast<const float2*>(g_K + (size_t)tok*D + cc);
                float2 vv = *reinterpret_cast<const float2*>(g_V + (size_t)tok*D + cc);
                float hn0 = acc[mt][nt][2*h]*irr,   hn1 = acc[mt][nt][2*h+1]*irr;
                float dp0 = cfv*(hn0*gam[cc] + kk.x - vv.x);
                float dp1 = cfv*(hn1*gam[cc+1] + kk.y - vv.y);
                float o0 = irr*(dp0*gam[cc]   - hn0*rd);
                float o1 = irr*(dp1*gam[cc+1] - hn1*rd);
                *reinterpret_cast<uint32_t*>(g_dHH + (size_t)tok*D + cc) = h2pack(o0, o1);
                colp[nt][0] += dp0*hn0;
                colp[nt][1] += dp1*hn1;
            }
        }
    __syncthreads();
    #pragma unroll
    for (int nt = 0; nt < 4; nt++)
        #pragma unroll
        for (int j = 0; j < 2; j++) {
            float v = colp[nt][j];
            v += __shfl_xor_sync(0xffffffffu, v, 4);
            v += __shfl_xor_sync(0xffffffffu, v, 8);
            v += __shfl_xor_sync(0xffffffffu, v, 16);
            if (group == 0) cs[wm*128 + COL_OF(nt) + j] = v;
        }
    __syncthreads();
    if (tid < 128) {
        float s = cs[tid] + cs[128 + tid] + cs[256 + tid] + cs[384 + tid];
        g_gfp[blockIdx.x*128 + tid] = s;
    }
}

// ---------------- G4: dZ = (dH @ w2^T) * GP ----------------
__global__ __launch_bounds__(NTHR, 2) void g4_da() {
    extern __shared__ char smraw[];
    int row0 = blockIdx.x*128, n0 = blockIdx.y*128;
    float acc[2][4][4] = {};
    mma_core<0,1,2>(g_dHH + (size_t)row0*D, D, g_w2H + (size_t)n0*D, D, acc, smraw);
    const int tid = threadIdx.x, lane = tid & 31, group = lane >> 2, tg = lane & 3;
    const int wid = tid >> 5, wm = wid & 3, wn = wid >> 2;
    #pragma unroll
    for (int mt = 0; mt < 2; mt++)
        #pragma unroll
        for (int h = 0; h < 2; h++) {
            int tok = row0 + ROW_OF(mt, h);
            size_t base = (size_t)tok*HID + n0;
            #pragma unroll
            for (int nt = 0; nt < 4; nt++) {
                int cc = COL_OF(nt);
                float2 gp = *reinterpret_cast<const float2*>(g_GP + base + cc);
                *reinterpret_cast<uint32_t*>(g_dZH + base + cc) =
                    h2pack(acc[mt][nt][2*h]*gp.x, acc[mt][nt][2*h+1]*gp.y);
            }
        }
}

// ---------------- G5 merged: y=0 w1p = K^T@dZ ; y=1 w2p = A^T@dH ----------------
__global__ __launch_bounds__(NTHR, 2) void g5_wp() {
    extern __shared__ char smraw[];
    int z = blockIdx.z, bh = z >> 3, sl = z & 7;
    int t0 = bh*4096 + sl*512;
    const __half* Ag; const __half* Bg; int lda, ldb;
    if (blockIdx.y == 0) {
        Ag = g_KH + (size_t)t0*D;                     lda = D;
        Bg = g_dZH + (size_t)t0*HID + blockIdx.x*128; ldb = HID;
    } else {
        Ag = g_AH + (size_t)t0*HID + blockIdx.x*128;  lda = HID;
        Bg = g_dHH + (size_t)t0*D;                    ldb = D;
    }
    float acc[2][4][4] = {};
    mma_core<1,0,8>(Ag, lda, Bg, ldb, acc, smraw);
    const int tid = threadIdx.x, lane = tid & 31, group = lane >> 2, tg = lane & 3;
    const int wid = tid >> 5, wm = wid & 3, wn = wid >> 2;
    if (blockIdx.y == 0) {
        float* C = g_w1p + (size_t)z*(D*HID);
        int n0 = blockIdx.x * 128;
        #pragma unroll
        for (int mt = 0; mt < 2; mt++)
            #pragma unroll
            for (int h = 0; h < 2; h++) {
                int r = ROW_OF(mt, h);
                #pragma unroll
                for (int nt = 0; nt < 4; nt++)
                    *reinterpret_cast<float2*>(C + (size_t)r*HID + n0 + COL_OF(nt)) =
                        make_float2(acc[mt][nt][2*h], acc[mt][nt][2*h+1]);
            }
    } else {
        float* C = g_w2p + (size_t)z*(HID*D);
        int m0 = blockIdx.x * 128;
        #pragma unroll
        for (int mt = 0; mt < 2; mt++)
            #pragma unroll
            for (int h = 0; h < 2; h++) {
                int r = m0 + ROW_OF(mt, h);
                #pragma unroll
                for (int nt = 0; nt < 4; nt++)
                    *reinterpret_cast<float2*>(C + (size_t)r*D + COL_OF(nt)) =
                        make_float2(acc[mt][nt][2*h], acc[mt][nt][2*h+1]);
            }
    }
}

// ---------------- reduce split-K partials (fp32) -> half finals + dgamma --------
__global__ void k_reduce() {
    int i = blockIdx.x*256 + threadIdx.x;
    if (i < BATCH*D*HID) {
        int bh = i >> 16, off = i & 65535;
        float s1 = 0, s2 = 0;
        #pragma unroll
        for (int s = 0; s < SLICES; s++) {
            s1 += g_w1p[(size_t)(bh*SLICES + s)*(D*HID) + off];
            s2 += g_w2p[(size_t)(bh*SLICES + s)*(HID*D) + off];
        }
        g_w1fH[i] = __float2half_rn(s1);
        g_w2fH[i] = __float2half_rn(s2);
    }
    if (i < BATCH*D) {
        int bh = i >> 7, col = i & 127;
        float s = 0;
        #pragma unroll
        for (int q = 0; q < 32; q++) s += g_gfp[(bh*32 + q)*128 + col];
        g_gf[i] = s;
    }
}

// ---------------- G6: A2 = gelu(Q @ w1f) ----------------
__global__ __launch_bounds__(NTHR, 2) void g6_z2() {
    extern __shared__ char smraw[];
    int row0 = blockIdx.x*128, n0 = blockIdx.y*128;
    int bh = row0 >> 12;
    float acc[2][4][4] = {};
    mma_core<0,0,2>(g_QH + (size_t)row0*D, D, g_w1fH + (size_t)bh*(D*HID) + n0, HID, acc, smraw);
    const int tid = threadIdx.x, lane = tid & 31, group = lane >> 2, tg = lane & 3;
    const int wid = tid >> 5, wm = wid & 3, wn = wid >> 2;
    #pragma unroll
    for (int mt = 0; mt < 2; mt++)
        #pragma unroll
        for (int h = 0; h < 2; h++) {
            int tok = row0 + ROW_OF(mt, h);
            size_t base = (size_t)tok*HID + n0;
            #pragma unroll
            for (int nt = 0; nt < 4; nt++) {
                int cc = COL_OF(nt);
                *reinterpret_cast<uint32_t*>(g_A2H + base + cc) =
                    h2pack(gelu_f(acc[mt][nt][2*h]), gelu_f(acc[mt][nt][2*h+1]));
            }
        }
}

// ---------------- G7: out = rmsnorm(A2 @ w2f)*gf + Q ----------------
__global__ __launch_bounds__(NTHR) void g7_out(float* __restrict__ out) {
    extern __shared__ char smraw[];
    __shared__ float gfs[128];
    const int tid = threadIdx.x;
    int row0 = blockIdx.x * 128;
    int bh = row0 >> 12;
    if (tid < 128) gfs[tid] = g_gf[bh*D + tid];
    float acc[2][4][4] = {};
    mma_core<0,0,8>(g_A2H + (size_t)row0*HID, HID, g_w2fH + (size_t)bh*(HID*D), D, acc, smraw);
    const int lane = tid & 31, group = lane >> 2, tg = lane & 3;
    const int wid = tid >> 5, wm = wid & 3, wn = wid >> 2;
    float* rs = reinterpret_cast<float*>(smraw);  // [4][128]
    #pragma unroll
    for (int mt = 0; mt < 2; mt++)
        #pragma unroll
        for (int h = 0; h < 2; h++) {
            float s = 0;
            #pragma unroll
            for (int nt = 0; nt < 4; nt++)
                s += acc[mt][nt][2*h]*acc[mt][nt][2*h] + acc[mt][nt][2*h+1]*acc[mt][nt][2*h+1];
            s += __shfl_xor_sync(0xffffffffu, s, 1);
            s += __shfl_xor_sync(0xffffffffu, s, 2);
            if (tg == 0) rs[wn*128 + ROW_OF(mt, h)] = s;
        }
    __syncthreads();
    #pragma unroll
    for (int mt = 0; mt < 2; mt++)
        #pragma unroll
        for (int h = 0; h < 2; h++) {
            int r = ROW_OF(mt, h), tok = row0 + r;
            float s = rs[r] + rs[128 + r] + rs[256 + r] + rs[384 + r];
            float irr = rsqrtf(s*(1.f/128.f) + 1e-6f);
            #pragma unroll
            for (int nt = 0; nt < 4; nt++) {
                int cc = COL_OF(nt);
                float2 qq = *reinterpret_cast<const float2*>(g_Q + (size_t)tok*D + cc);
                *reinterpret_cast<float2*>(out + (size_t)tok*D + cc) =
                    make_float2(acc[mt][nt][2*h]*irr*gfs[cc] + qq.x,
                                acc[mt][nt][2*h+1]*irr*gfs[cc+1] + qq.y);
            }
        }
}

// ---------------- launch ----------------
extern "C" void kernel_launch(void* const* d_in, const int* in_sizes, int n_in,
                              void* d_out, int out_size) {
    (void)in_sizes; (void)n_in; (void)out_size;
    const float* seq  = (const float*)d_in[0];
    const float* wk   = (const float*)d_in[1];
    const float* wv   = (const float*)d_in[2];
    const float* wq   = (const float*)d_in[3];
    const float* wlr  = (const float*)d_in[4];
    const float* blr  = (const float*)d_in[5];
    const float* wdec = (const float*)d_in[6];
    const float* bdec = (const float*)d_in[7];
    const float* wmom = (const float*)d_in[8];
    const float* bmom = (const float*)d_in[9];
    const float* gamma= (const float*)d_in[10];
    const float* w1   = (const float*)d_in[11];
    const float* w2   = (const float*)d_in[12];
    float* out = (float*)d_out;

    cudaFuncSetAttribute(g1_proj,  cudaFuncAttributeMaxDynamicSharedMemorySize, SMEM_DYN);
    cudaFuncSetAttribute(g2_zgelu, cudaFuncAttributeMaxDynamicSharedMemorySize, SMEM_DYN);
    cudaFuncSetAttribute(g3_hback, cudaFuncAttributeMaxDynamicSharedMemorySize, SMEM_DYN);
    cudaFuncSetAttribute(g4_da,    cudaFuncAttributeMaxDynamicSharedMemorySize, SMEM_DYN);
    cudaFuncSetAttribute(g5_wp,    cudaFuncAttributeMaxDynamicSharedMemorySize, SMEM_DYN);
    cudaFuncSetAttribute(g6_z2,    cudaFuncAttributeMaxDynamicSharedMemorySize, SMEM_DYN);
    cudaFuncSetAttribute(g7_out,   cudaFuncAttributeMaxDynamicSharedMemorySize, SMEM_DYN);

    k_half  <<<2224, 256>>>(seq, wk, wv, wq, w1, w2);
    k_dots  <<<BATCH*NC, 128>>>(seq, wlr, blr, wdec, bdec, wmom, bmom);
    k_coef  <<<1, 32>>>();
    g1_proj <<<dim3(NTOK/128, 1, 3), NTHR, SMEM_DYN>>>();
    g2_zgelu<<<dim3(NTOK/128, HID/128), NTHR, SMEM_DYN>>>();
    g3_hback<<<NTOK/128, NTHR, SMEM_DYN>>>(gamma);
    g4_da   <<<dim3(NTOK/128, HID/128), NTHR, SMEM_DYN>>>();
    g5_wp   <<<dim3(HID/128, 2, BATCH*SLICES), NTHR, SMEM_DYN>>>();
    k_reduce<<<(BATCH*D*HID)/256, 256>>>();
    g6_z2   <<<dim3(NTOK/128, HID/128), NTHR, SMEM_DYN>>>();
    g7_out  <<<NTOK/128, NTHR, SMEM_DYN>>>(out);
}